// round 4
// baseline (speedup 1.0000x reference)
#include <cuda_runtime.h>
#include <math.h>

#define N_NODES  50000
#define N_EDGES  800000
#define N_GRAPHS 512
#define IN_DIM   128
#define HID      256
#define OUT_DIM  40

// ---------------- scratch (device globals; no allocation allowed) ----------------
__device__ float g_agg[(size_t)N_NODES * HID];
__device__ float g_tmp[(size_t)N_NODES * HID];
__device__ float g_hA [(size_t)N_NODES * HID];
__device__ float g_hB [(size_t)N_NODES * HID];
__device__ int   g_deg[N_NODES];
__device__ int   g_rowptr[N_NODES + 1];
__device__ int   g_cursor[N_NODES];
__device__ int   g_eidx[N_EDGES];
__device__ float g_pool[N_GRAPHS * HID];

// ---------------- packed f32x2 helpers (Blackwell FFMA2) ----------------
__device__ __forceinline__ unsigned long long dup_f32x2(float x) {
    unsigned long long r;
    asm("mov.b64 %0, {%1, %1};" : "=l"(r) : "f"(x));
    return r;
}
__device__ __forceinline__ void ffma2(unsigned long long& d,
                                      unsigned long long a,
                                      unsigned long long b) {
    asm("fma.rn.f32x2 %0, %1, %2, %0;" : "+l"(d) : "l"(a), "l"(b));
}
__device__ __forceinline__ void unpack2(unsigned long long u, float& lo, float& hi) {
    asm("mov.b64 {%0, %1}, %2;" : "=f"(lo), "=f"(hi) : "l"(u));
}

// ---------------- CSR build ----------------
__global__ void hist_k(const int* __restrict__ dst) {
    int e = blockIdx.x * blockDim.x + threadIdx.x;
    if (e < N_EDGES) atomicAdd(&g_deg[dst[e]], 1);
}

// single-block exclusive scan of g_deg -> g_rowptr (50001 entries)
__global__ void scan_k() {
    __shared__ int buf[1024];
    __shared__ int carry;
    int tid = threadIdx.x;
    if (tid == 0) carry = 0;
    __syncthreads();
    for (int base = 0; base < N_NODES; base += 1024) {
        int v = (base + tid < N_NODES) ? g_deg[base + tid] : 0;
        buf[tid] = v;
        __syncthreads();
        for (int off = 1; off < 1024; off <<= 1) {
            int t = (tid >= off) ? buf[tid - off] : 0;
            __syncthreads();
            buf[tid] += t;
            __syncthreads();
        }
        int c0 = carry;
        if (base + tid < N_NODES) g_rowptr[base + tid] = buf[tid] - v + c0;
        __syncthreads();
        if (tid == 0) carry += buf[1023];
        __syncthreads();
    }
    if (tid == 0) g_rowptr[N_NODES] = carry;
}

__global__ void fill_k(const int* __restrict__ src, const int* __restrict__ dst) {
    int e = blockIdx.x * blockDim.x + threadIdx.x;
    if (e < N_EDGES) {
        int d = dst[e];
        int p = atomicAdd(&g_cursor[d], 1);
        g_eidx[p] = src[e];
    }
}

// ---------------- neighbor aggregation (gather via CSR) ----------------
// thread = (node, float4 chunk). Warp covers chunks of ONE node -> no
// divergence. 2-way unrolled edge loop for memory-level parallelism.
__global__ void agg_k(const float* __restrict__ X, float* __restrict__ AGG, int D4) {
    int gid  = blockIdx.x * blockDim.x + threadIdx.x;
    int node = gid / D4;
    int c    = gid - node * D4;
    int s = g_rowptr[node];
    int e = g_rowptr[node + 1];
    const float4* x4 = (const float4*)X;
    float4 acc0 = make_float4(0.f, 0.f, 0.f, 0.f);
    float4 acc1 = make_float4(0.f, 0.f, 0.f, 0.f);
    int j = s;
    for (; j + 1 < e; j += 2) {
        int s0 = g_eidx[j];
        int s1 = g_eidx[j + 1];
        float4 v0 = __ldg(&x4[(size_t)s0 * D4 + c]);
        float4 v1 = __ldg(&x4[(size_t)s1 * D4 + c]);
        acc0.x += v0.x; acc0.y += v0.y; acc0.z += v0.z; acc0.w += v0.w;
        acc1.x += v1.x; acc1.y += v1.y; acc1.z += v1.z; acc1.w += v1.w;
    }
    if (j < e) {
        int s0 = g_eidx[j];
        float4 v0 = __ldg(&x4[(size_t)s0 * D4 + c]);
        acc0.x += v0.x; acc0.y += v0.y; acc0.z += v0.z; acc0.w += v0.w;
    }
    acc0.x += acc1.x; acc0.y += acc1.y; acc0.z += acc1.z; acc0.w += acc1.w;
    ((float4*)AGG)[(size_t)node * D4 + c] = acc0;
}

// ---------------- fused SGEMM with packed FFMA2 inner product ----------------
// C[N,M] = epilogue( A' @ B + bias ), A' = FUSE_ADD ? (1+eps)*A + A2 : A
// epilogue: relu, then optional BN (eval mode): v*gamma/sqrt(1+1e-5) + beta
// Accumulators packed along M: acc2[i2][j] holds rows (2*i2, 2*i2+1), col j.
// A pairs are free (adjacent regs from the float4 shared load); B scalars are
// duplicated with one mov.b64 each (alu pipe, off the fma critical path).
template<bool FUSE_ADD, bool BN_OUT>
__global__ void __launch_bounds__(256, 2) gemm_k(
    const float* __restrict__ A, const float* __restrict__ A2,
    const float* __restrict__ epsp,
    const float* __restrict__ B, const float* __restrict__ bias,
    const float* __restrict__ gamma, const float* __restrict__ beta,
    float* __restrict__ C, int N, int K, int M)
{
    const int BM = 128, BN = 128, BK = 16, TM = 8, TN = 8;
    __shared__ float As[BK][BM];
    __shared__ float Bs[BK][BN];
    int tid = threadIdx.x;
    int tx = tid & 15, ty = tid >> 4;
    int rowBase = blockIdx.y * BM;
    int colBase = blockIdx.x * BN;

    float alpha = 1.0f;
    if (FUSE_ADD) alpha = 1.0f + __ldg(epsp);

    unsigned long long acc2[TM / 2][TN];
    #pragma unroll
    for (int i = 0; i < TM / 2; i++)
        #pragma unroll
        for (int j = 0; j < TN; j++) acc2[i][j] = 0ull;

    int a_r = tid >> 2;          // 0..63
    int a_c = (tid & 3) << 2;    // 0,4,8,12
    int b_r = tid >> 5;          // 0..7
    int b_c = (tid & 31) << 2;   // 0..124

    union F4U2 { float4 f4; unsigned long long u2[2]; };

    for (int k0 = 0; k0 < K; k0 += BK) {
        #pragma unroll
        for (int i = 0; i < 2; i++) {
            int r = a_r + i * 64;
            int grow = rowBase + r;
            float4 v = make_float4(0.f, 0.f, 0.f, 0.f);
            if (grow < N) {
                v = *(const float4*)(A + (size_t)grow * K + k0 + a_c);
                if (FUSE_ADD) {
                    float4 w = *(const float4*)(A2 + (size_t)grow * K + k0 + a_c);
                    v.x = alpha * v.x + w.x; v.y = alpha * v.y + w.y;
                    v.z = alpha * v.z + w.z; v.w = alpha * v.w + w.w;
                }
            }
            As[a_c + 0][r] = v.x; As[a_c + 1][r] = v.y;
            As[a_c + 2][r] = v.z; As[a_c + 3][r] = v.w;
        }
        #pragma unroll
        for (int i = 0; i < 2; i++) {
            int r = b_r + i * 8;
            *(float4*)&Bs[r][b_c] =
                *(const float4*)(B + (size_t)(k0 + r) * M + colBase + b_c);
        }
        __syncthreads();

        #pragma unroll
        for (int kk = 0; kk < BK; kk++) {
            // A fragment: 8 rows -> 4 packed pairs, straight from LDS.128 regs.
            F4U2 a0, a1;
            a0.f4 = *(const float4*)&As[kk][ty * TM];
            a1.f4 = *(const float4*)&As[kk][ty * TM + 4];
            unsigned long long ap[4] = { a0.u2[0], a0.u2[1], a1.u2[0], a1.u2[1] };

            // B fragment: 8 scalars, each duplicated into a f32x2 lane pair.
            float4 bf0 = *(const float4*)&Bs[kk][tx * TN];
            float4 bf1 = *(const float4*)&Bs[kk][tx * TN + 4];
            unsigned long long bp[8];
            bp[0] = dup_f32x2(bf0.x); bp[1] = dup_f32x2(bf0.y);
            bp[2] = dup_f32x2(bf0.z); bp[3] = dup_f32x2(bf0.w);
            bp[4] = dup_f32x2(bf1.x); bp[5] = dup_f32x2(bf1.y);
            bp[6] = dup_f32x2(bf1.z); bp[7] = dup_f32x2(bf1.w);

            #pragma unroll
            for (int i = 0; i < TM / 2; i++)
                #pragma unroll
                for (int j = 0; j < TN; j++)
                    ffma2(acc2[i][j], ap[i], bp[j]);
        }
        __syncthreads();
    }

    const float bnmul = rsqrtf(1.0f + 1e-5f);
    #pragma unroll
    for (int i2 = 0; i2 < TM / 2; i2++) {
        int row0 = rowBase + ty * TM + 2 * i2;
        #pragma unroll
        for (int j = 0; j < TN; j++) {
            int col = colBase + tx * TN + j;
            float lo, hi;
            unpack2(acc2[i2][j], lo, hi);
            float bcol = __ldg(&bias[col]);
            float gcol = 0.f, betac = 0.f;
            if (BN_OUT) { gcol = __ldg(&gamma[col]) * bnmul; betac = __ldg(&beta[col]); }
            if (row0 < N) {
                float v = fmaxf(lo + bcol, 0.f);
                if (BN_OUT) v = v * gcol + betac;
                C[(size_t)row0 * M + col] = v;
            }
            if (row0 + 1 < N) {
                float v = fmaxf(hi + bcol, 0.f);
                if (BN_OUT) v = v * gcol + betac;
                C[(size_t)(row0 + 1) * M + col] = v;
            }
        }
    }
}

// ---------------- pooling (batch is sorted -> binary search ranges) ----------------
__device__ __forceinline__ int lbound(const int* a, int n, int v) {
    int lo = 0, hi = n;
    while (lo < hi) { int m = (lo + hi) >> 1; if (a[m] < v) lo = m + 1; else hi = m; }
    return lo;
}

__global__ void pool_k(const float* __restrict__ H, const int* __restrict__ batch) {
    int g = blockIdx.x;
    int t = threadIdx.x;
    __shared__ int ss, se;
    if (t == 0)  ss = lbound(batch, N_NODES, g);
    if (t == 32) se = lbound(batch, N_NODES, g + 1);
    __syncthreads();
    int start = ss, end = se;
    int c = t & 63, sub = t >> 6;     // 64 chunks x 4 node-strides
    const float4* h4 = (const float4*)H;
    float4 acc = make_float4(0.f, 0.f, 0.f, 0.f);
    for (int i = start + sub; i < end; i += 4) {
        float4 v = h4[(size_t)i * 64 + c];
        acc.x += v.x; acc.y += v.y; acc.z += v.z; acc.w += v.w;
    }
    __shared__ float4 red[256];
    red[t] = acc;
    __syncthreads();
    if (sub == 0) {
        float4 a = red[c], b = red[c + 64], c2 = red[c + 128], d = red[c + 192];
        int cnt = end - start;
        float inv = 1.0f / (float)(cnt > 1 ? cnt : 1);
        float4 o;
        o.x = (a.x + b.x + c2.x + d.x) * inv;
        o.y = (a.y + b.y + c2.y + d.y) * inv;
        o.z = (a.z + b.z + c2.z + d.z) * inv;
        o.w = (a.w + b.w + c2.w + d.w) * inv;
        ((float4*)g_pool)[g * 64 + c] = o;
    }
}

// ---------------- final MLP + log_softmax (one block per graph) ----------------
__global__ void final_k(const float* __restrict__ lw1, const float* __restrict__ lb1,
                        const float* __restrict__ lw2, const float* __restrict__ lb2,
                        float* __restrict__ out)
{
    int g = blockIdx.x, t = threadIdx.x;
    __shared__ float p[HID], o1[HID], o2[OUT_DIM];
    __shared__ float s_m, s_l;
    p[t] = g_pool[g * HID + t];
    __syncthreads();
    float acc = __ldg(&lb1[t]);
    for (int k = 0; k < HID; k++) acc = fmaf(p[k], __ldg(&lw1[k * HID + t]), acc);
    o1[t] = fmaxf(acc, 0.f);
    __syncthreads();
    if (t < OUT_DIM) {
        float a = __ldg(&lb2[t]);
        for (int k = 0; k < HID; k++) a = fmaf(o1[k], __ldg(&lw2[k * OUT_DIM + t]), a);
        o2[t] = a;
    }
    __syncthreads();
    if (t == 0) {
        float m = -1e30f;
        for (int j = 0; j < OUT_DIM; j++) m = fmaxf(m, o2[j]);
        float s = 0.f;
        for (int j = 0; j < OUT_DIM; j++) s += expf(o2[j] - m);
        s_m = m; s_l = logf(s);
    }
    __syncthreads();
    if (t < OUT_DIM) out[g * OUT_DIM + t] = o2[t] - s_m - s_l;
}

// ---------------- launcher ----------------
extern "C" void kernel_launch(void* const* d_in, const int* in_sizes, int n_in,
                              void* d_out, int out_size)
{
    const float* x    = (const float*)d_in[0];
    const int*   ei   = (const int*)  d_in[1];
    const int*   batch= (const int*)  d_in[2];
    const float* w1a  = (const float*)d_in[3];
    const float* b1a  = (const float*)d_in[4];
    const float* w2a  = (const float*)d_in[5];
    const float* b2a  = (const float*)d_in[6];
    const float* ga   = (const float*)d_in[7];
    const float* bba  = (const float*)d_in[8];
    const float* eps0 = (const float*)d_in[9];
    const float* w1r  = (const float*)d_in[10];
    const float* b1r  = (const float*)d_in[11];
    const float* w2r  = (const float*)d_in[12];
    const float* b2r  = (const float*)d_in[13];
    const float* gr   = (const float*)d_in[14];
    const float* br   = (const float*)d_in[15];
    const float* epsr = (const float*)d_in[16];
    const float* lw1  = (const float*)d_in[17];
    const float* lb1  = (const float*)d_in[18];
    const float* lw2  = (const float*)d_in[19];
    const float* lb2  = (const float*)d_in[20];
    float* out = (float*)d_out;

    const int* src = ei;
    const int* dst = ei + N_EDGES;

    void *agg_p, *tmp_p, *hA_p, *hB_p, *deg_p, *rp_p, *cur_p;
    cudaGetSymbolAddress(&agg_p, g_agg);
    cudaGetSymbolAddress(&tmp_p, g_tmp);
    cudaGetSymbolAddress(&hA_p,  g_hA);
    cudaGetSymbolAddress(&hB_p,  g_hB);
    cudaGetSymbolAddress(&deg_p, g_deg);
    cudaGetSymbolAddress(&rp_p,  g_rowptr);
    cudaGetSymbolAddress(&cur_p, g_cursor);

    float* agg = (float*)agg_p;
    float* tmp = (float*)tmp_p;
    float* hA  = (float*)hA_p;
    float* hB  = (float*)hB_p;

    // --- CSR build (once per call, reused by all 4 layers) ---
    cudaMemsetAsync(deg_p, 0, N_NODES * sizeof(int));
    hist_k<<<(N_EDGES + 255) / 256, 256>>>(dst);
    scan_k<<<1, 1024>>>();
    cudaMemcpyAsync(cur_p, rp_p, N_NODES * sizeof(int), cudaMemcpyDeviceToDevice);
    fill_k<<<(N_EDGES + 255) / 256, 256>>>(src, dst);

    dim3 grid(HID / 128, (N_NODES + 127) / 128);

    // --- layer 1 (IN_DIM -> HID) ---
    agg_k<<<(N_NODES * (IN_DIM / 4)) / 256, 256>>>(x, agg, IN_DIM / 4);
    gemm_k<true,  false><<<grid, 256>>>(x,   agg, eps0, w1a, b1a, nullptr, nullptr,
                                        tmp, N_NODES, IN_DIM, HID);
    gemm_k<false, true ><<<grid, 256>>>(tmp, nullptr, nullptr, w2a, b2a, ga, bba,
                                        hA,  N_NODES, HID, HID);

    // --- layers 2..4 (HID -> HID) ---
    const float* hin = hA;
    float* hout = hB;
    for (int i = 0; i < 3; i++) {
        agg_k<<<(N_NODES * (HID / 4)) / 256, 256>>>(hin, agg, HID / 4);
        gemm_k<true,  false><<<grid, 256>>>(hin, agg, epsr + i,
                                            w1r + (size_t)i * HID * HID, b1r + i * HID,
                                            nullptr, nullptr, tmp, N_NODES, HID, HID);
        gemm_k<false, true ><<<grid, 256>>>(tmp, nullptr, nullptr,
                                            w2r + (size_t)i * HID * HID, b2r + i * HID,
                                            gr + i * HID, br + i * HID,
                                            hout, N_NODES, HID, HID);
        const float* t2 = hin; hin = hout; hout = (float*)t2;
    }

    // --- pooling + head ---
    pool_k<<<N_GRAPHS, 256>>>(hin, batch);
    final_k<<<N_GRAPHS, 256>>>(lw1, lb1, lw2, lb2, out);
}

// round 5
// speedup vs baseline: 1.0299x; 1.0299x over previous
#include <cuda_runtime.h>
#include <math.h>
#include <stdint.h>

#define N_NODES  50000
#define N_EDGES  800000
#define N_GRAPHS 512
#define IN_DIM   128
#define HID      256
#define OUT_DIM  40

// ---------------- scratch (device globals; no allocation allowed) ----------------
__device__ float g_agg[(size_t)N_NODES * HID];
__device__ float g_tmp[(size_t)N_NODES * HID];
__device__ float g_hA [(size_t)N_NODES * HID];
__device__ float g_hB [(size_t)N_NODES * HID];
__device__ int   g_deg[N_NODES];
__device__ int   g_rowptr[N_NODES + 1];
__device__ int   g_cursor[N_NODES];
__device__ int   g_eidx[N_EDGES];
__device__ float g_pool[N_GRAPHS * HID];

// ---------------- CSR build ----------------
__global__ void hist_k(const int* __restrict__ dst) {
    int e = blockIdx.x * blockDim.x + threadIdx.x;
    if (e < N_EDGES) atomicAdd(&g_deg[dst[e]], 1);
}

__global__ void scan_k() {
    __shared__ int buf[1024];
    __shared__ int carry;
    int tid = threadIdx.x;
    if (tid == 0) carry = 0;
    __syncthreads();
    for (int base = 0; base < N_NODES; base += 1024) {
        int v = (base + tid < N_NODES) ? g_deg[base + tid] : 0;
        buf[tid] = v;
        __syncthreads();
        for (int off = 1; off < 1024; off <<= 1) {
            int t = (tid >= off) ? buf[tid - off] : 0;
            __syncthreads();
            buf[tid] += t;
            __syncthreads();
        }
        int c0 = carry;
        if (base + tid < N_NODES) g_rowptr[base + tid] = buf[tid] - v + c0;
        __syncthreads();
        if (tid == 0) carry += buf[1023];
        __syncthreads();
    }
    if (tid == 0) g_rowptr[N_NODES] = carry;
}

__global__ void fill_k(const int* __restrict__ src, const int* __restrict__ dst) {
    int e = blockIdx.x * blockDim.x + threadIdx.x;
    if (e < N_EDGES) {
        int d = dst[e];
        int p = atomicAdd(&g_cursor[d], 1);
        g_eidx[p] = src[e];
    }
}

// ---------------- neighbor aggregation (gather via CSR) ----------------
__global__ void agg_k(const float* __restrict__ X, float* __restrict__ AGG, int D4) {
    int gid  = blockIdx.x * blockDim.x + threadIdx.x;
    int node = gid / D4;
    int c    = gid - node * D4;
    int s = g_rowptr[node];
    int e = g_rowptr[node + 1];
    const float4* x4 = (const float4*)X;
    float4 acc0 = make_float4(0.f, 0.f, 0.f, 0.f);
    float4 acc1 = make_float4(0.f, 0.f, 0.f, 0.f);
    int j = s;
    for (; j + 1 < e; j += 2) {
        int s0 = g_eidx[j];
        int s1 = g_eidx[j + 1];
        float4 v0 = __ldg(&x4[(size_t)s0 * D4 + c]);
        float4 v1 = __ldg(&x4[(size_t)s1 * D4 + c]);
        acc0.x += v0.x; acc0.y += v0.y; acc0.z += v0.z; acc0.w += v0.w;
        acc1.x += v1.x; acc1.y += v1.y; acc1.z += v1.z; acc1.w += v1.w;
    }
    if (j < e) {
        int s0 = g_eidx[j];
        float4 v0 = __ldg(&x4[(size_t)s0 * D4 + c]);
        acc0.x += v0.x; acc0.y += v0.y; acc0.z += v0.z; acc0.w += v0.w;
    }
    acc0.x += acc1.x; acc0.y += acc1.y; acc0.z += acc1.z; acc0.w += acc1.w;
    ((float4*)AGG)[(size_t)node * D4 + c] = acc0;
}

// ---------------- tf32 helpers ----------------
__device__ __forceinline__ float tf32_rn(float x) {
    uint32_t u;
    asm("cvt.rna.tf32.f32 %0, %1;" : "=r"(u) : "f"(x));
    return __uint_as_float(u);
}
__device__ __forceinline__ void split_tf32(float x, float& hi, float& lo) {
    hi = tf32_rn(x);
    lo = tf32_rn(x - hi);
}
__device__ __forceinline__ void mma_tf32(float* c, const float* a, const float* b) {
    asm volatile(
        "mma.sync.aligned.m16n8k8.row.col.f32.tf32.tf32.f32 "
        "{%0,%1,%2,%3}, {%4,%5,%6,%7}, {%8,%9}, {%0,%1,%2,%3};"
        : "+f"(c[0]), "+f"(c[1]), "+f"(c[2]), "+f"(c[3])
        : "r"(__float_as_uint(a[0])), "r"(__float_as_uint(a[1])),
          "r"(__float_as_uint(a[2])), "r"(__float_as_uint(a[3])),
          "r"(__float_as_uint(b[0])), "r"(__float_as_uint(b[1])));
}

// ---------------- tensor-core SGEMM (3xTF32, fp32-accurate) ----------------
// C[N,M] = epilogue( A' @ B + bias ), A' = FUSE_ADD ? (1+eps)*A + A2 : A
// Block 128x128, 8 warps (warp tile 32x64 = 2x8 m16n8k8 tiles), BK=16.
// A/B are split into tf32 hi/lo at SMEM-fill; inner product does
// hi*hi + hi*lo + lo*hi (error ~2^-22, fp32-grade).
template<bool FUSE_ADD, bool BN_OUT>
__global__ void __launch_bounds__(256, 1) gemm_tc(
    const float* __restrict__ A, const float* __restrict__ A2,
    const float* __restrict__ epsp,
    const float* __restrict__ B, const float* __restrict__ bias,
    const float* __restrict__ gamma, const float* __restrict__ beta,
    float* __restrict__ C, int N, int K, int M)
{
    __shared__ float AsH[128][18];   // [m][k], pad->conflict-light frag loads
    __shared__ float AsL[128][18];
    __shared__ float BsH[16][136];   // [k][n], stride 136 -> conflict-free
    __shared__ float BsL[16][136];

    int tid = threadIdx.x;
    int lane = tid & 31;
    int wid  = tid >> 5;
    int warp_m = wid & 3;     // 0..3  (M)
    int warp_n = wid >> 2;    // 0..1  (N)
    int g  = lane >> 2;       // 0..7
    int tg = lane & 3;        // 0..3

    int rowBase = blockIdx.y * 128;
    int colBase = blockIdx.x * 128;

    float alpha = 1.0f;
    if (FUSE_ADD) alpha = 1.0f + __ldg(epsp);

    float acc[2][8][4];
    #pragma unroll
    for (int mt = 0; mt < 2; mt++)
        #pragma unroll
        for (int nt = 0; nt < 8; nt++)
            #pragma unroll
            for (int q = 0; q < 4; q++) acc[mt][nt][q] = 0.f;

    int a_r = tid >> 2;          // 0..63
    int a_c = (tid & 3) << 2;    // 0,4,8,12
    int b_r = tid >> 5;          // 0..7
    int b_c = (tid & 31) << 2;   // 0..124

    for (int k0 = 0; k0 < K; k0 += 16) {
        // ---- fill A (with optional GIN fuse), split hi/lo ----
        #pragma unroll
        for (int i = 0; i < 2; i++) {
            int r = a_r + i * 64;
            int grow = rowBase + r;
            float4 v = make_float4(0.f, 0.f, 0.f, 0.f);
            if (grow < N) {
                v = *(const float4*)(A + (size_t)grow * K + k0 + a_c);
                if (FUSE_ADD) {
                    float4 w = *(const float4*)(A2 + (size_t)grow * K + k0 + a_c);
                    v.x = alpha * v.x + w.x; v.y = alpha * v.y + w.y;
                    v.z = alpha * v.z + w.z; v.w = alpha * v.w + w.w;
                }
            }
            float hi, lo;
            split_tf32(v.x, hi, lo); AsH[r][a_c + 0] = hi; AsL[r][a_c + 0] = lo;
            split_tf32(v.y, hi, lo); AsH[r][a_c + 1] = hi; AsL[r][a_c + 1] = lo;
            split_tf32(v.z, hi, lo); AsH[r][a_c + 2] = hi; AsL[r][a_c + 2] = lo;
            split_tf32(v.w, hi, lo); AsH[r][a_c + 3] = hi; AsL[r][a_c + 3] = lo;
        }
        // ---- fill B, split hi/lo ----
        #pragma unroll
        for (int i = 0; i < 2; i++) {
            int r = b_r + i * 8;
            float4 v = *(const float4*)(B + (size_t)(k0 + r) * M + colBase + b_c);
            float hi, lo;
            split_tf32(v.x, hi, lo); BsH[r][b_c + 0] = hi; BsL[r][b_c + 0] = lo;
            split_tf32(v.y, hi, lo); BsH[r][b_c + 1] = hi; BsL[r][b_c + 1] = lo;
            split_tf32(v.z, hi, lo); BsH[r][b_c + 2] = hi; BsL[r][b_c + 2] = lo;
            split_tf32(v.w, hi, lo); BsH[r][b_c + 3] = hi; BsL[r][b_c + 3] = lo;
        }
        __syncthreads();

        #pragma unroll
        for (int kk = 0; kk < 2; kk++) {
            int k8 = kk * 8;
            // A fragments: m16n8k8 .row mapping
            float aH[2][4], aL[2][4];
            #pragma unroll
            for (int mt = 0; mt < 2; mt++) {
                int am = warp_m * 32 + mt * 16;
                aH[mt][0] = AsH[am + g    ][k8 + tg];
                aH[mt][1] = AsH[am + g + 8][k8 + tg];
                aH[mt][2] = AsH[am + g    ][k8 + tg + 4];
                aH[mt][3] = AsH[am + g + 8][k8 + tg + 4];
                aL[mt][0] = AsL[am + g    ][k8 + tg];
                aL[mt][1] = AsL[am + g + 8][k8 + tg];
                aL[mt][2] = AsL[am + g    ][k8 + tg + 4];
                aL[mt][3] = AsL[am + g + 8][k8 + tg + 4];
            }
            // B fragments: .col mapping (b0=(k=tg,n), b1=(k=tg+4,n))
            float bH[8][2], bL[8][2];
            #pragma unroll
            for (int nt = 0; nt < 8; nt++) {
                int bn = warp_n * 64 + nt * 8 + g;
                bH[nt][0] = BsH[k8 + tg    ][bn];
                bH[nt][1] = BsH[k8 + tg + 4][bn];
                bL[nt][0] = BsL[k8 + tg    ][bn];
                bL[nt][1] = BsL[k8 + tg + 4][bn];
            }
            #pragma unroll
            for (int mt = 0; mt < 2; mt++)
                #pragma unroll
                for (int nt = 0; nt < 8; nt++) {
                    mma_tf32(acc[mt][nt], aH[mt], bH[nt]);
                    mma_tf32(acc[mt][nt], aH[mt], bL[nt]);
                    mma_tf32(acc[mt][nt], aL[mt], bH[nt]);
                }
        }
        __syncthreads();
    }

    // ---- epilogue: bias, relu, optional BN; float2 stores (adjacent cols) ----
    const float bnmul = rsqrtf(1.0f + 1e-5f);
    #pragma unroll
    for (int nt = 0; nt < 8; nt++) {
        int col0 = colBase + warp_n * 64 + nt * 8 + 2 * tg;
        float b0 = __ldg(&bias[col0]);
        float b1 = __ldg(&bias[col0 + 1]);
        float g0 = 0.f, g1 = 0.f, be0 = 0.f, be1 = 0.f;
        if (BN_OUT) {
            g0 = __ldg(&gamma[col0]) * bnmul;  be0 = __ldg(&beta[col0]);
            g1 = __ldg(&gamma[col0 + 1]) * bnmul; be1 = __ldg(&beta[col0 + 1]);
        }
        #pragma unroll
        for (int mt = 0; mt < 2; mt++) {
            int r0 = rowBase + warp_m * 32 + mt * 16 + g;
            #pragma unroll
            for (int half = 0; half < 2; half++) {
                int row = r0 + half * 8;
                if (row < N) {
                    float v0 = fmaxf(acc[mt][nt][2 * half + 0] + b0, 0.f);
                    float v1 = fmaxf(acc[mt][nt][2 * half + 1] + b1, 0.f);
                    if (BN_OUT) { v0 = v0 * g0 + be0; v1 = v1 * g1 + be1; }
                    float2 o = make_float2(v0, v1);
                    *(float2*)(C + (size_t)row * M + col0) = o;
                }
            }
        }
    }
}

// ---------------- pooling (batch is sorted -> binary search ranges) ----------------
__device__ __forceinline__ int lbound(const int* a, int n, int v) {
    int lo = 0, hi = n;
    while (lo < hi) { int m = (lo + hi) >> 1; if (a[m] < v) lo = m + 1; else hi = m; }
    return lo;
}

__global__ void pool_k(const float* __restrict__ H, const int* __restrict__ batch) {
    int g = blockIdx.x;
    int t = threadIdx.x;
    __shared__ int ss, se;
    if (t == 0)  ss = lbound(batch, N_NODES, g);
    if (t == 32) se = lbound(batch, N_NODES, g + 1);
    __syncthreads();
    int start = ss, end = se;
    int c = t & 63, sub = t >> 6;
    const float4* h4 = (const float4*)H;
    float4 acc = make_float4(0.f, 0.f, 0.f, 0.f);
    for (int i = start + sub; i < end; i += 4) {
        float4 v = h4[(size_t)i * 64 + c];
        acc.x += v.x; acc.y += v.y; acc.z += v.z; acc.w += v.w;
    }
    __shared__ float4 red[256];
    red[t] = acc;
    __syncthreads();
    if (sub == 0) {
        float4 a = red[c], b = red[c + 64], c2 = red[c + 128], d = red[c + 192];
        int cnt = end - start;
        float inv = 1.0f / (float)(cnt > 1 ? cnt : 1);
        float4 o;
        o.x = (a.x + b.x + c2.x + d.x) * inv;
        o.y = (a.y + b.y + c2.y + d.y) * inv;
        o.z = (a.z + b.z + c2.z + d.z) * inv;
        o.w = (a.w + b.w + c2.w + d.w) * inv;
        ((float4*)g_pool)[g * 64 + c] = o;
    }
}

// ---------------- final MLP + log_softmax (one block per graph) ----------------
__global__ void final_k(const float* __restrict__ lw1, const float* __restrict__ lb1,
                        const float* __restrict__ lw2, const float* __restrict__ lb2,
                        float* __restrict__ out)
{
    int g = blockIdx.x, t = threadIdx.x;
    __shared__ float p[HID], o1[HID], o2[OUT_DIM];
    __shared__ float s_m, s_l;
    p[t] = g_pool[g * HID + t];
    __syncthreads();
    float acc = __ldg(&lb1[t]);
    for (int k = 0; k < HID; k++) acc = fmaf(p[k], __ldg(&lw1[k * HID + t]), acc);
    o1[t] = fmaxf(acc, 0.f);
    __syncthreads();
    if (t < OUT_DIM) {
        float a = __ldg(&lb2[t]);
        for (int k = 0; k < HID; k++) a = fmaf(o1[k], __ldg(&lw2[k * OUT_DIM + t]), a);
        o2[t] = a;
    }
    __syncthreads();
    if (t == 0) {
        float m = -1e30f;
        for (int j = 0; j < OUT_DIM; j++) m = fmaxf(m, o2[j]);
        float s = 0.f;
        for (int j = 0; j < OUT_DIM; j++) s += expf(o2[j] - m);
        s_m = m; s_l = logf(s);
    }
    __syncthreads();
    if (t < OUT_DIM) out[g * OUT_DIM + t] = o2[t] - s_m - s_l;
}

// ---------------- launcher ----------------
extern "C" void kernel_launch(void* const* d_in, const int* in_sizes, int n_in,
                              void* d_out, int out_size)
{
    const float* x    = (const float*)d_in[0];
    const int*   ei   = (const int*)  d_in[1];
    const int*   batch= (const int*)  d_in[2];
    const float* w1a  = (const float*)d_in[3];
    const float* b1a  = (const float*)d_in[4];
    const float* w2a  = (const float*)d_in[5];
    const float* b2a  = (const float*)d_in[6];
    const float* ga   = (const float*)d_in[7];
    const float* bba  = (const float*)d_in[8];
    const float* eps0 = (const float*)d_in[9];
    const float* w1r  = (const float*)d_in[10];
    const float* b1r  = (const float*)d_in[11];
    const float* w2r  = (const float*)d_in[12];
    const float* b2r  = (const float*)d_in[13];
    const float* gr   = (const float*)d_in[14];
    const float* br   = (const float*)d_in[15];
    const float* epsr = (const float*)d_in[16];
    const float* lw1  = (const float*)d_in[17];
    const float* lb1  = (const float*)d_in[18];
    const float* lw2  = (const float*)d_in[19];
    const float* lb2  = (const float*)d_in[20];
    float* out = (float*)d_out;

    const int* src = ei;
    const int* dst = ei + N_EDGES;

    void *agg_p, *tmp_p, *hA_p, *hB_p, *deg_p, *rp_p, *cur_p;
    cudaGetSymbolAddress(&agg_p, g_agg);
    cudaGetSymbolAddress(&tmp_p, g_tmp);
    cudaGetSymbolAddress(&hA_p,  g_hA);
    cudaGetSymbolAddress(&hB_p,  g_hB);
    cudaGetSymbolAddress(&deg_p, g_deg);
    cudaGetSymbolAddress(&rp_p,  g_rowptr);
    cudaGetSymbolAddress(&cur_p, g_cursor);

    float* agg = (float*)agg_p;
    float* tmp = (float*)tmp_p;
    float* hA  = (float*)hA_p;
    float* hB  = (float*)hB_p;

    // --- CSR build (once per call, reused by all 4 layers) ---
    cudaMemsetAsync(deg_p, 0, N_NODES * sizeof(int));
    hist_k<<<(N_EDGES + 255) / 256, 256>>>(dst);
    scan_k<<<1, 1024>>>();
    cudaMemcpyAsync(cur_p, rp_p, N_NODES * sizeof(int), cudaMemcpyDeviceToDevice);
    fill_k<<<(N_EDGES + 255) / 256, 256>>>(src, dst);

    dim3 grid(HID / 128, (N_NODES + 127) / 128);   // (2, 391)

    // --- layer 1 (IN_DIM -> HID) ---
    agg_k<<<(N_NODES * (IN_DIM / 4)) / 256, 256>>>(x, agg, IN_DIM / 4);
    gemm_tc<true,  false><<<grid, 256>>>(x,   agg, eps0, w1a, b1a, nullptr, nullptr,
                                         tmp, N_NODES, IN_DIM, HID);
    gemm_tc<false, true ><<<grid, 256>>>(tmp, nullptr, nullptr, w2a, b2a, ga, bba,
                                         hA,  N_NODES, HID, HID);

    // --- layers 2..4 (HID -> HID) ---
    const float* hin = hA;
    float* hout = hB;
    for (int i = 0; i < 3; i++) {
        agg_k<<<(N_NODES * (HID / 4)) / 256, 256>>>(hin, agg, HID / 4);
        gemm_tc<true,  false><<<grid, 256>>>(hin, agg, epsr + i,
                                             w1r + (size_t)i * HID * HID, b1r + i * HID,
                                             nullptr, nullptr, tmp, N_NODES, HID, HID);
        gemm_tc<false, true ><<<grid, 256>>>(tmp, nullptr, nullptr,
                                             w2r + (size_t)i * HID * HID, b2r + i * HID,
                                             gr + i * HID, br + i * HID,
                                             hout, N_NODES, HID, HID);
        const float* t2 = hin; hin = hout; hout = (float*)t2;
    }

    // --- pooling + head ---
    pool_k<<<N_GRAPHS, 256>>>(hin, batch);
    final_k<<<N_GRAPHS, 256>>>(lw1, lb1, lw2, lb2, out);
}

// round 8
// speedup vs baseline: 1.4946x; 1.4512x over previous
#include <cuda_runtime.h>
#include <cuda_bf16.h>
#include <math.h>
#include <stdint.h>

#define N_NODES  50000
#define N_EDGES  800000
#define N_GRAPHS 512
#define IN_DIM   128
#define HID      256
#define OUT_DIM  40

// ---------------- scratch (device globals; no allocation allowed) ----------------
__device__ float g_agg[(size_t)N_NODES * HID];
__device__ float g_tmp[(size_t)N_NODES * HID];
__device__ float g_hA [(size_t)N_NODES * HID];
__device__ float g_hB [(size_t)N_NODES * HID];
__device__ int   g_deg[N_NODES];
__device__ int   g_rowptr[N_NODES + 1];
__device__ int   g_cursor[N_NODES];
__device__ int   g_eidx[N_EDGES];
__device__ float g_pool[N_GRAPHS * HID];

// ---------------- CSR build ----------------
__global__ void hist_k(const int* __restrict__ dst) {
    int e = blockIdx.x * blockDim.x + threadIdx.x;
    if (e < N_EDGES) atomicAdd(&g_deg[dst[e]], 1);
}

__global__ void scan_k() {
    __shared__ int buf[1024];
    __shared__ int carry;
    int tid = threadIdx.x;
    if (tid == 0) carry = 0;
    __syncthreads();
    for (int base = 0; base < N_NODES; base += 1024) {
        int v = (base + tid < N_NODES) ? g_deg[base + tid] : 0;
        buf[tid] = v;
        __syncthreads();
        for (int off = 1; off < 1024; off <<= 1) {
            int t = (tid >= off) ? buf[tid - off] : 0;
            __syncthreads();
            buf[tid] += t;
            __syncthreads();
        }
        int c0 = carry;
        if (base + tid < N_NODES) g_rowptr[base + tid] = buf[tid] - v + c0;
        __syncthreads();
        if (tid == 0) carry += buf[1023];
        __syncthreads();
    }
    if (tid == 0) g_rowptr[N_NODES] = carry;
}

__global__ void fill_k(const int* __restrict__ src, const int* __restrict__ dst) {
    int e = blockIdx.x * blockDim.x + threadIdx.x;
    if (e < N_EDGES) {
        int d = dst[e];
        int p = atomicAdd(&g_cursor[d], 1);
        g_eidx[p] = src[e];
    }
}

// ---------------- neighbor aggregation (gather via CSR) ----------------
__global__ void agg_k(const float* __restrict__ X, float* __restrict__ AGG, int D4) {
    int gid  = blockIdx.x * blockDim.x + threadIdx.x;
    int node = gid / D4;
    int c    = gid - node * D4;
    int s = g_rowptr[node];
    int e = g_rowptr[node + 1];
    const float4* x4 = (const float4*)X;
    float4 acc0 = make_float4(0.f, 0.f, 0.f, 0.f);
    float4 acc1 = make_float4(0.f, 0.f, 0.f, 0.f);
    int j = s;
    for (; j + 1 < e; j += 2) {
        int s0 = g_eidx[j];
        int s1 = g_eidx[j + 1];
        float4 v0 = __ldg(&x4[(size_t)s0 * D4 + c]);
        float4 v1 = __ldg(&x4[(size_t)s1 * D4 + c]);
        acc0.x += v0.x; acc0.y += v0.y; acc0.z += v0.z; acc0.w += v0.w;
        acc1.x += v1.x; acc1.y += v1.y; acc1.z += v1.z; acc1.w += v1.w;
    }
    if (j < e) {
        int s0 = g_eidx[j];
        float4 v0 = __ldg(&x4[(size_t)s0 * D4 + c]);
        acc0.x += v0.x; acc0.y += v0.y; acc0.z += v0.z; acc0.w += v0.w;
    }
    acc0.x += acc1.x; acc0.y += acc1.y; acc0.z += acc1.z; acc0.w += acc1.w;
    ((float4*)AGG)[(size_t)node * D4 + c] = acc0;
}

// ---------------- bf16 helpers ----------------
__device__ __forceinline__ uint32_t pkbf(float a, float b) {
    __nv_bfloat162 t = __floats2bfloat162_rn(a, b);
    uint32_t u; memcpy(&u, &t, 4); return u;
}
__device__ __forceinline__ void split2(float v, float& h, float& l) {
    h = __bfloat162float(__float2bfloat16(v));
    l = v - h;            // exact; bf16-rounded on store
}
__device__ __forceinline__ uint32_t s2u(const void* p) {
    uint32_t a;
    asm("{ .reg .u64 t; cvta.to.shared.u64 t, %1; cvt.u32.u64 %0, t; }"
        : "=r"(a) : "l"(p));
    return a;
}
__device__ __forceinline__ void ldmx4(uint32_t* r, uint32_t addr) {
    asm volatile("ldmatrix.sync.aligned.m8n8.x4.shared.b16 {%0,%1,%2,%3}, [%4];"
                 : "=r"(r[0]), "=r"(r[1]), "=r"(r[2]), "=r"(r[3]) : "r"(addr));
}
__device__ __forceinline__ void mma_bf16(float* c, const uint32_t* a, const uint32_t* b) {
    asm volatile(
        "mma.sync.aligned.m16n8k16.row.col.f32.bf16.bf16.f32 "
        "{%0,%1,%2,%3}, {%4,%5,%6,%7}, {%8,%9}, {%0,%1,%2,%3};"
        : "+f"(c[0]), "+f"(c[1]), "+f"(c[2]), "+f"(c[3])
        : "r"(a[0]), "r"(a[1]), "r"(a[2]), "r"(a[3]), "r"(b[0]), "r"(b[1]));
}

// ---------------- bf16 2-limb tensor GEMM ----------------
// C[N,M] = epilogue( A' @ B + bias ), A' = FUSE_ADD ? (1+eps)*A + A2 : A.
// Block 128x128, 8 warps (warp tile 32x64), K-tile 32 (2 x k16).
// A,B split hi/lo bf16 at fill; products hh + hl + lh (drop ll ~2^-18).
#define KT 32
#define APAD 40   // row stride in halves; 80B -> ldmatrix banks (5r)%8 all-distinct

template<bool FUSE_ADD, bool BN_OUT>
__global__ void __launch_bounds__(256, 1) gemm_bf(
    const float* __restrict__ A, const float* __restrict__ A2,
    const float* __restrict__ epsp,
    const float* __restrict__ B, const float* __restrict__ bias,
    const float* __restrict__ gamma, const float* __restrict__ beta,
    float* __restrict__ C, int N, int K, int M)
{
    __shared__ __nv_bfloat16 AH[128][APAD];
    __shared__ __nv_bfloat16 AL[128][APAD];
    __shared__ __nv_bfloat16 BH[128][APAD];   // BH[n][k] = hi(W[k][colBase+n])
    __shared__ __nv_bfloat16 BL[128][APAD];

    int tid = threadIdx.x;
    int lane = tid & 31;
    int wid  = tid >> 5;
    int warp_m = wid & 3;    // m: 4 x 32
    int warp_n = wid >> 2;   // n: 2 x 64
    int g  = lane >> 2;      // 0..7
    int tg = lane & 3;       // 0..3

    int rowBase = blockIdx.y * 128;
    int colBase = blockIdx.x * 128;

    float alpha = 1.0f;
    if (FUSE_ADD) alpha = 1.0f + __ldg(epsp);

    float acc[2][8][4];
    #pragma unroll
    for (int mt = 0; mt < 2; mt++)
        #pragma unroll
        for (int nt = 0; nt < 8; nt++)
            #pragma unroll
            for (int q = 0; q < 4; q++) acc[mt][nt][q] = 0.f;

    // ldmatrix base addresses (lane-dependent, loop-invariant)
    // A: row = warp_m*32 + mt*16 + (lane&15); col halves = (lane>>4)*8 (+ksub*16)
    uint32_t aAddr[2];
    #pragma unroll
    for (int mt = 0; mt < 2; mt++) {
        int r = warp_m * 32 + mt * 16 + (lane & 15);
        int c = (lane >> 4) * 8;
        aAddr[mt] = s2u(&AH[r][c]);
    }
    // B: n = warp_n*64 + ntp*16 + (lane>>4)*8 + (lane&7); col = ((lane>>3)&1)*8 (+ksub*16)
    uint32_t bAddr[4];
    #pragma unroll
    for (int ntp = 0; ntp < 4; ntp++) {
        int n = warp_n * 64 + ntp * 16 + (lane >> 4) * 8 + (lane & 7);
        int c = ((lane >> 3) & 1) * 8;
        bAddr[ntp] = s2u(&BH[n][c]);
    }
    const uint32_t dAL = (uint32_t)((const char*)&AL[0][0] - (const char*)&AH[0][0]);
    const uint32_t dBL = (uint32_t)((const char*)&BL[0][0] - (const char*)&BH[0][0]);

    for (int k0 = 0; k0 < K; k0 += KT) {
        // ---- fill A' (fused GIN add), split hi/lo ----
        {
            int r  = tid >> 1;
            int kh = (tid & 1) * 16;
            int grow = rowBase + r;
            bool valid = grow < N;
            #pragma unroll
            for (int i = 0; i < 4; i++) {
                int kk = kh + i * 4;
                float4 v = make_float4(0.f, 0.f, 0.f, 0.f);
                if (valid) {
                    v = *(const float4*)(A + (size_t)grow * K + k0 + kk);
                    if (FUSE_ADD) {
                        float4 w = *(const float4*)(A2 + (size_t)grow * K + k0 + kk);
                        v.x = alpha * v.x + w.x; v.y = alpha * v.y + w.y;
                        v.z = alpha * v.z + w.z; v.w = alpha * v.w + w.w;
                    }
                }
                float h0,l0,h1,l1,h2,l2,h3,l3;
                split2(v.x,h0,l0); split2(v.y,h1,l1);
                split2(v.z,h2,l2); split2(v.w,h3,l3);
                *(uint32_t*)&AH[r][kk]     = pkbf(h0, h1);
                *(uint32_t*)&AH[r][kk + 2] = pkbf(h2, h3);
                *(uint32_t*)&AL[r][kk]     = pkbf(l0, l1);
                *(uint32_t*)&AL[r][kk + 2] = pkbf(l2, l3);
            }
        }
        // ---- fill B^T: BH[n][k] = W[(k0+k)*M + colBase+n] ----
        {
            int n  = tid >> 1;
            int kh = (tid & 1) * 16;
            #pragma unroll
            for (int i = 0; i < 8; i++) {
                int kk = kh + i * 2;
                float v0 = __ldg(&B[(size_t)(k0 + kk)     * M + colBase + n]);
                float v1 = __ldg(&B[(size_t)(k0 + kk + 1) * M + colBase + n]);
                float h0,l0,h1,l1;
                split2(v0,h0,l0); split2(v1,h1,l1);
                *(uint32_t*)&BH[n][kk] = pkbf(h0, h1);
                *(uint32_t*)&BL[n][kk] = pkbf(l0, l1);
            }
        }
        __syncthreads();

        #pragma unroll
        for (int ksub = 0; ksub < 2; ksub++) {
            uint32_t koff = ksub * 32;   // 16 halves = 32 bytes
            uint32_t aH[2][4], aL[2][4];
            #pragma unroll
            for (int mt = 0; mt < 2; mt++) {
                ldmx4(aH[mt], aAddr[mt] + koff);
                ldmx4(aL[mt], aAddr[mt] + koff + dAL);
            }
            uint32_t bH[8][2], bL[8][2];
            #pragma unroll
            for (int ntp = 0; ntp < 4; ntp++) {
                uint32_t t[4];
                ldmx4(t, bAddr[ntp] + koff);
                bH[2*ntp][0] = t[0]; bH[2*ntp][1] = t[1];
                bH[2*ntp+1][0] = t[2]; bH[2*ntp+1][1] = t[3];
                ldmx4(t, bAddr[ntp] + koff + dBL);
                bL[2*ntp][0] = t[0]; bL[2*ntp][1] = t[1];
                bL[2*ntp+1][0] = t[2]; bL[2*ntp+1][1] = t[3];
            }
            // product-major order: 16 independent chains per pass
            #pragma unroll
            for (int mt = 0; mt < 2; mt++)
                #pragma unroll
                for (int nt = 0; nt < 8; nt++)
                    mma_bf16(acc[mt][nt], aH[mt], bH[nt]);
            #pragma unroll
            for (int mt = 0; mt < 2; mt++)
                #pragma unroll
                for (int nt = 0; nt < 8; nt++)
                    mma_bf16(acc[mt][nt], aH[mt], bL[nt]);
            #pragma unroll
            for (int mt = 0; mt < 2; mt++)
                #pragma unroll
                for (int nt = 0; nt < 8; nt++)
                    mma_bf16(acc[mt][nt], aL[mt], bH[nt]);
        }
        __syncthreads();
    }

    // ---- epilogue ----
    const float bnmul = rsqrtf(1.0f + 1e-5f);
    #pragma unroll
    for (int nt = 0; nt < 8; nt++) {
        int col0 = colBase + warp_n * 64 + nt * 8 + 2 * tg;
        float b0 = __ldg(&bias[col0]);
        float b1 = __ldg(&bias[col0 + 1]);
        float g0 = 0.f, g1 = 0.f, be0 = 0.f, be1 = 0.f;
        if (BN_OUT) {
            g0 = __ldg(&gamma[col0]) * bnmul;     be0 = __ldg(&beta[col0]);
            g1 = __ldg(&gamma[col0 + 1]) * bnmul; be1 = __ldg(&beta[col0 + 1]);
        }
        #pragma unroll
        for (int mt = 0; mt < 2; mt++) {
            int r0 = rowBase + warp_m * 32 + mt * 16 + g;
            #pragma unroll
            for (int half = 0; half < 2; half++) {
                int row = r0 + half * 8;
                if (row < N) {
                    float v0 = fmaxf(acc[mt][nt][2 * half + 0] + b0, 0.f);
                    float v1 = fmaxf(acc[mt][nt][2 * half + 1] + b1, 0.f);
                    if (BN_OUT) { v0 = v0 * g0 + be0; v1 = v1 * g1 + be1; }
                    *(float2*)(C + (size_t)row * M + col0) = make_float2(v0, v1);
                }
            }
        }
    }
}

// ---------------- pooling (batch is sorted -> binary search ranges) ----------------
__device__ __forceinline__ int lbound(const int* a, int n, int v) {
    int lo = 0, hi = n;
    while (lo < hi) { int m = (lo + hi) >> 1; if (a[m] < v) lo = m + 1; else hi = m; }
    return lo;
}

__global__ void pool_k(const float* __restrict__ H, const int* __restrict__ batch) {
    int g = blockIdx.x;
    int t = threadIdx.x;
    __shared__ int ss, se;
    if (t == 0)  ss = lbound(batch, N_NODES, g);
    if (t == 32) se = lbound(batch, N_NODES, g + 1);
    __syncthreads();
    int start = ss, end = se;
    int c = t & 63, sub = t >> 6;
    const float4* h4 = (const float4*)H;
    float4 acc = make_float4(0.f, 0.f, 0.f, 0.f);
    for (int i = start + sub; i < end; i += 4) {
        float4 v = h4[(size_t)i * 64 + c];
        acc.x += v.x; acc.y += v.y; acc.z += v.z; acc.w += v.w;
    }
    __shared__ float4 red[256];
    red[t] = acc;
    __syncthreads();
    if (sub == 0) {
        float4 a = red[c], b = red[c + 64], c2 = red[c + 128], d = red[c + 192];
        int cnt = end - start;
        float inv = 1.0f / (float)(cnt > 1 ? cnt : 1);
        float4 o;
        o.x = (a.x + b.x + c2.x + d.x) * inv;
        o.y = (a.y + b.y + c2.y + d.y) * inv;
        o.z = (a.z + b.z + c2.z + d.z) * inv;
        o.w = (a.w + b.w + c2.w + d.w) * inv;
        ((float4*)g_pool)[g * 64 + c] = o;
    }
}

// ---------------- final MLP + log_softmax (one block per graph) ----------------
__global__ void final_k(const float* __restrict__ lw1, const float* __restrict__ lb1,
                        const float* __restrict__ lw2, const float* __restrict__ lb2,
                        float* __restrict__ out)
{
    int g = blockIdx.x, t = threadIdx.x;
    __shared__ float p[HID], o1[HID], o2[OUT_DIM];
    __shared__ float s_m, s_l;
    p[t] = g_pool[g * HID + t];
    __syncthreads();
    float acc = __ldg(&lb1[t]);
    for (int k = 0; k < HID; k++) acc = fmaf(p[k], __ldg(&lw1[k * HID + t]), acc);
    o1[t] = fmaxf(acc, 0.f);
    __syncthreads();
    if (t < OUT_DIM) {
        float a = __ldg(&lb2[t]);
        for (int k = 0; k < HID; k++) a = fmaf(o1[k], __ldg(&lw2[k * OUT_DIM + t]), a);
        o2[t] = a;
    }
    __syncthreads();
    if (t == 0) {
        float m = -1e30f;
        for (int j = 0; j < OUT_DIM; j++) m = fmaxf(m, o2[j]);
        float s = 0.f;
        for (int j = 0; j < OUT_DIM; j++) s += expf(o2[j] - m);
        s_m = m; s_l = logf(s);
    }
    __syncthreads();
    if (t < OUT_DIM) out[g * OUT_DIM + t] = o2[t] - s_m - s_l;
}

// ---------------- launcher ----------------
extern "C" void kernel_launch(void* const* d_in, const int* in_sizes, int n_in,
                              void* d_out, int out_size)
{
    const float* x    = (const float*)d_in[0];
    const int*   ei   = (const int*)  d_in[1];
    const int*   batch= (const int*)  d_in[2];
    const float* w1a  = (const float*)d_in[3];
    const float* b1a  = (const float*)d_in[4];
    const float* w2a  = (const float*)d_in[5];
    const float* b2a  = (const float*)d_in[6];
    const float* ga   = (const float*)d_in[7];
    const float* bba  = (const float*)d_in[8];
    const float* eps0 = (const float*)d_in[9];
    const float* w1r  = (const float*)d_in[10];
    const float* b1r  = (const float*)d_in[11];
    const float* w2r  = (const float*)d_in[12];
    const float* b2r  = (const float*)d_in[13];
    const float* gr   = (const float*)d_in[14];
    const float* br   = (const float*)d_in[15];
    const float* epsr = (const float*)d_in[16];
    const float* lw1  = (const float*)d_in[17];
    const float* lb1  = (const float*)d_in[18];
    const float* lw2  = (const float*)d_in[19];
    const float* lb2  = (const float*)d_in[20];
    float* out = (float*)d_out;

    const int* src = ei;
    const int* dst = ei + N_EDGES;

    void *agg_p, *tmp_p, *hA_p, *hB_p, *deg_p, *rp_p, *cur_p;
    cudaGetSymbolAddress(&agg_p, g_agg);
    cudaGetSymbolAddress(&tmp_p, g_tmp);
    cudaGetSymbolAddress(&hA_p,  g_hA);
    cudaGetSymbolAddress(&hB_p,  g_hB);
    cudaGetSymbolAddress(&deg_p, g_deg);
    cudaGetSymbolAddress(&rp_p,  g_rowptr);
    cudaGetSymbolAddress(&cur_p, g_cursor);

    float* agg = (float*)agg_p;
    float* tmp = (float*)tmp_p;
    float* hA  = (float*)hA_p;
    float* hB  = (float*)hB_p;

    // --- CSR build (once per call, reused by all 4 layers) ---
    cudaMemsetAsync(deg_p, 0, N_NODES * sizeof(int));
    hist_k<<<(N_EDGES + 255) / 256, 256>>>(dst);
    scan_k<<<1, 1024>>>();
    cudaMemcpyAsync(cur_p, rp_p, N_NODES * sizeof(int), cudaMemcpyDeviceToDevice);
    fill_k<<<(N_EDGES + 255) / 256, 256>>>(src, dst);

    dim3 grid(HID / 128, (N_NODES + 127) / 128);   // (2, 391)

    // --- layer 1 (IN_DIM -> HID) ---
    agg_k<<<(N_NODES * (IN_DIM / 4)) / 256, 256>>>(x, agg, IN_DIM / 4);
    gemm_bf<true,  false><<<grid, 256>>>(x,   agg, eps0, w1a, b1a, nullptr, nullptr,
                                         tmp, N_NODES, IN_DIM, HID);
    gemm_bf<false, true ><<<grid, 256>>>(tmp, nullptr, nullptr, w2a, b2a, ga, bba,
                                         hA,  N_NODES, HID, HID);

    // --- layers 2..4 (HID -> HID) ---
    const float* hin = hA;
    float* hout = hB;
    for (int i = 0; i < 3; i++) {
        agg_k<<<(N_NODES * (HID / 4)) / 256, 256>>>(hin, agg, HID / 4);
        gemm_bf<true,  false><<<grid, 256>>>(hin, agg, epsr + i,
                                             w1r + (size_t)i * HID * HID, b1r + i * HID,
                                             nullptr, nullptr, tmp, N_NODES, HID, HID);
        gemm_bf<false, true ><<<grid, 256>>>(tmp, nullptr, nullptr,
                                             w2r + (size_t)i * HID * HID, b2r + i * HID,
                                             gr + i * HID, br + i * HID,
                                             hout, N_NODES, HID, HID);
        const float* t2 = hin; hin = hout; hout = (float*)t2;
    }

    // --- pooling + head ---
    pool_k<<<N_GRAPHS, 256>>>(hin, batch);
    final_k<<<N_GRAPHS, 256>>>(lw1, lb1, lw2, lb2, out);
}

// round 9
// speedup vs baseline: 1.8390x; 1.2304x over previous
#include <cuda_runtime.h>
#include <cuda_bf16.h>
#include <math.h>
#include <stdint.h>

#define N_NODES  50000
#define N_EDGES  800000
#define N_GRAPHS 512
#define IN_DIM   128
#define HID      256
#define OUT_DIM  40

// ---------------- scratch (device globals; no allocation allowed) ----------------
__device__ float g_hA [(size_t)N_NODES * HID];
__device__ float g_hB [(size_t)N_NODES * HID];
__device__ __nv_bfloat16 g_AH[(size_t)N_NODES * HID];
__device__ __nv_bfloat16 g_AL[(size_t)N_NODES * HID];
__device__ __nv_bfloat16 g_TH[(size_t)N_NODES * HID];
__device__ __nv_bfloat16 g_TL[(size_t)N_NODES * HID];
#define W_TOTAL 491520   // 256x128 + 7x 256x256, transposed K-major
__device__ __nv_bfloat16 g_WH[W_TOTAL];
__device__ __nv_bfloat16 g_WL[W_TOTAL];
__device__ int   g_deg[N_NODES];
__device__ int   g_rowptr[N_NODES + 1];
__device__ int   g_cursor[N_NODES];
__device__ int   g_eidx[N_EDGES];
__device__ float g_pool[N_GRAPHS * HID];

// ---------------- helpers ----------------
__device__ __forceinline__ uint32_t pkbf(float a, float b) {
    __nv_bfloat162 t = __floats2bfloat162_rn(a, b);
    uint32_t u; memcpy(&u, &t, 4); return u;
}
__device__ __forceinline__ void split2(float v, float& h, float& l) {
    h = __bfloat162float(__float2bfloat16(v));
    l = v - h;
}
__device__ __forceinline__ uint32_t s2u(const void* p) {
    uint32_t a;
    asm("{ .reg .u64 t; cvta.to.shared.u64 t, %1; cvt.u32.u64 %0, t; }"
        : "=r"(a) : "l"(p));
    return a;
}
__device__ __forceinline__ void ldmx4(uint32_t* r, uint32_t addr) {
    asm volatile("ldmatrix.sync.aligned.m8n8.x4.shared.b16 {%0,%1,%2,%3}, [%4];"
                 : "=r"(r[0]), "=r"(r[1]), "=r"(r[2]), "=r"(r[3]) : "r"(addr));
}
__device__ __forceinline__ void mma_bf16(float* c, const uint32_t* a, const uint32_t* b) {
    asm volatile(
        "mma.sync.aligned.m16n8k16.row.col.f32.bf16.bf16.f32 "
        "{%0,%1,%2,%3}, {%4,%5,%6,%7}, {%8,%9}, {%0,%1,%2,%3};"
        : "+f"(c[0]), "+f"(c[1]), "+f"(c[2]), "+f"(c[3])
        : "r"(a[0]), "r"(a[1]), "r"(a[2]), "r"(a[3]), "r"(b[0]), "r"(b[1]));
}
__device__ __forceinline__ void cpa16(uint32_t dst, const void* src, uint32_t vsz) {
    asm volatile("cp.async.cg.shared.global [%0], [%1], 16, %2;"
                 :: "r"(dst), "l"(src), "r"(vsz));
}
#define CP_COMMIT() asm volatile("cp.async.commit_group;" ::: "memory")
#define CP_WAIT1()  asm volatile("cp.async.wait_group 1;" ::: "memory")
#define CP_WAIT0()  asm volatile("cp.async.wait_group 0;" ::: "memory")

// ---------------- CSR build ----------------
__global__ void hist_k(const int* __restrict__ dst) {
    int e = blockIdx.x * blockDim.x + threadIdx.x;
    if (e < N_EDGES) atomicAdd(&g_deg[dst[e]], 1);
}

__global__ void scan_k() {
    __shared__ int buf[1024];
    __shared__ int carry;
    int tid = threadIdx.x;
    if (tid == 0) carry = 0;
    __syncthreads();
    for (int base = 0; base < N_NODES; base += 1024) {
        int v = (base + tid < N_NODES) ? g_deg[base + tid] : 0;
        buf[tid] = v;
        __syncthreads();
        for (int off = 1; off < 1024; off <<= 1) {
            int t = (tid >= off) ? buf[tid - off] : 0;
            __syncthreads();
            buf[tid] += t;
            __syncthreads();
        }
        int c0 = carry;
        if (base + tid < N_NODES) g_rowptr[base + tid] = buf[tid] - v + c0;
        __syncthreads();
        if (tid == 0) carry += buf[1023];
        __syncthreads();
    }
    if (tid == 0) g_rowptr[N_NODES] = carry;
}

__global__ void fill_k(const int* __restrict__ src, const int* __restrict__ dst) {
    int e = blockIdx.x * blockDim.x + threadIdx.x;
    if (e < N_EDGES) {
        int d = dst[e];
        int p = atomicAdd(&g_cursor[d], 1);
        g_eidx[p] = src[e];
    }
}

// ---------------- weight pre-split + transpose: dst[n][k] = split(W[k][n]) ----------------
__global__ void wt_k(const float* __restrict__ W, __nv_bfloat16* __restrict__ dH,
                     __nv_bfloat16* __restrict__ dL, int K, int M) {
    int idx = blockIdx.x * blockDim.x + threadIdx.x;   // n*K + k
    if (idx >= K * M) return;
    int n = idx / K, k = idx - n * K;
    float v = __ldg(&W[(size_t)k * M + n]);
    float h, l; split2(v, h, l);
    dH[idx] = __float2bfloat16(h);
    dL[idx] = __float2bfloat16(l);
}

// ---------------- fused aggregation + GIN add + limb split ----------------
// A' = (1+eps)*X + sum_neighbors X ; writes bf16 hi/lo limb arrays [N][D]
__global__ void aggf_k(const float* __restrict__ X, const float* __restrict__ epsp,
                       int D4, __nv_bfloat16* __restrict__ AH,
                       __nv_bfloat16* __restrict__ AL) {
    int gid  = blockIdx.x * blockDim.x + threadIdx.x;
    int node = gid / D4;
    int c    = gid - node * D4;
    int s = g_rowptr[node];
    int e = g_rowptr[node + 1];
    const float4* x4 = (const float4*)X;
    float4 acc0 = make_float4(0.f, 0.f, 0.f, 0.f);
    float4 acc1 = make_float4(0.f, 0.f, 0.f, 0.f);
    int j = s;
    for (; j + 1 < e; j += 2) {
        int s0 = g_eidx[j];
        int s1 = g_eidx[j + 1];
        float4 v0 = __ldg(&x4[(size_t)s0 * D4 + c]);
        float4 v1 = __ldg(&x4[(size_t)s1 * D4 + c]);
        acc0.x += v0.x; acc0.y += v0.y; acc0.z += v0.z; acc0.w += v0.w;
        acc1.x += v1.x; acc1.y += v1.y; acc1.z += v1.z; acc1.w += v1.w;
    }
    if (j < e) {
        int s0 = g_eidx[j];
        float4 v0 = __ldg(&x4[(size_t)s0 * D4 + c]);
        acc0.x += v0.x; acc0.y += v0.y; acc0.z += v0.z; acc0.w += v0.w;
    }
    float alpha = 1.0f + __ldg(epsp);
    float4 xs = __ldg(&x4[(size_t)node * D4 + c]);
    float4 v;
    v.x = alpha * xs.x + acc0.x + acc1.x;
    v.y = alpha * xs.y + acc0.y + acc1.y;
    v.z = alpha * xs.z + acc0.z + acc1.z;
    v.w = alpha * xs.w + acc0.w + acc1.w;
    float h0,l0,h1,l1,h2,l2,h3,l3;
    split2(v.x,h0,l0); split2(v.y,h1,l1); split2(v.z,h2,l2); split2(v.w,h3,l3);
    size_t base = (size_t)node * (D4 * 4) + c * 4;
    *(uint2*)&AH[base] = make_uint2(pkbf(h0, h1), pkbf(h2, h3));
    *(uint2*)&AL[base] = make_uint2(pkbf(l0, l1), pkbf(l2, l3));
}

// ---------------- pipelined bf16 2-limb tensor GEMM ----------------
// C = epilogue( A @ W + bias ); A limbs [N][K] bf16, W limbs transposed [256][K].
// Block 128x128, 8 warps, K-tile 32, 2-stage cp.async double buffer.
// EPI_LIMB: write relu result as bf16 limbs (CH/CL). else fp32 with ReLU+BN.
#define KT 32
#define APAD 40                       // halves; 80B rows
#define OAH 0u
#define OAL 10240u
#define OBH 20480u
#define OBL 30720u
#define STG 40960u
#define GSMEM (2 * STG)

template<bool EPI_LIMB, bool BN_OUT>
__global__ void __launch_bounds__(256, 1) gemm_p(
    const __nv_bfloat16* __restrict__ AH, const __nv_bfloat16* __restrict__ AL,
    const __nv_bfloat16* __restrict__ WH, const __nv_bfloat16* __restrict__ WL,
    const float* __restrict__ bias,
    const float* __restrict__ gamma, const float* __restrict__ beta,
    float* __restrict__ Cf, __nv_bfloat16* __restrict__ CH,
    __nv_bfloat16* __restrict__ CL,
    int N, int K, int M)
{
    extern __shared__ char smem[];
    uint32_t sb = s2u(smem);
    int tid = threadIdx.x;
    int lane = tid & 31;
    int wid  = tid >> 5;
    int warp_m = wid & 3;
    int warp_n = wid >> 2;
    int g  = lane >> 2;
    int tg = lane & 3;

    int rowBase = blockIdx.y * 128;
    int colBase = blockIdx.x * 128;

    // fill-thread mapping: row fr (0..127), k-half fk (0 or 16 halves)
    int fr = tid >> 1;
    int fk = (tid & 1) * 16;
    bool avalid = (rowBase + fr) < N;
    size_t aBase = (size_t)(avalid ? (rowBase + fr) : 0) * K + fk;
    size_t bBase = (size_t)(colBase + fr) * K + fk;
    uint32_t avsz = avalid ? 16u : 0u;
    uint32_t aDst = fr * 80 + fk * 2;

#define ISSUE_FILL(stage, k0) do {                                      \
    uint32_t s_ = sb + (stage) * STG;                                   \
    const char* pAH = (const char*)(AH + aBase + (k0));                 \
    const char* pAL = (const char*)(AL + aBase + (k0));                 \
    cpa16(s_ + OAH + aDst,      pAH,      avsz);                        \
    cpa16(s_ + OAH + aDst + 16, pAH + 16, avsz);                        \
    cpa16(s_ + OAL + aDst,      pAL,      avsz);                        \
    cpa16(s_ + OAL + aDst + 16, pAL + 16, avsz);                        \
    const char* pBH = (const char*)(WH + bBase + (k0));                 \
    const char* pBL = (const char*)(WL + bBase + (k0));                 \
    cpa16(s_ + OBH + aDst,      pBH,      16u);                         \
    cpa16(s_ + OBH + aDst + 16, pBH + 16, 16u);                         \
    cpa16(s_ + OBL + aDst,      pBL,      16u);                         \
    cpa16(s_ + OBL + aDst + 16, pBL + 16, 16u);                         \
} while (0)

    float acc[2][8][4];
    #pragma unroll
    for (int mt = 0; mt < 2; mt++)
        #pragma unroll
        for (int nt = 0; nt < 8; nt++)
            #pragma unroll
            for (int q = 0; q < 4; q++) acc[mt][nt][q] = 0.f;

    // ldmatrix relative offsets (within a stage)
    uint32_t aRel[2];
    #pragma unroll
    for (int mt = 0; mt < 2; mt++) {
        int r = warp_m * 32 + mt * 16 + (lane & 15);
        int c = (lane >> 4) * 8;
        aRel[mt] = OAH + r * 80 + c * 2;
    }
    uint32_t bRel[4];
    #pragma unroll
    for (int ntp = 0; ntp < 4; ntp++) {
        int n = warp_n * 64 + ntp * 16 + (lane >> 4) * 8 + (lane & 7);
        int c = ((lane >> 3) & 1) * 8;
        bRel[ntp] = OBH + n * 80 + c * 2;
    }
    const uint32_t dL = OAL - OAH;   // 10240, same for B

    ISSUE_FILL(0, 0);
    CP_COMMIT();

    const int nkt = K / KT;
    for (int kt = 0; kt < nkt; kt++) {
        if (kt + 1 < nkt) {
            ISSUE_FILL((kt + 1) & 1, (kt + 1) * KT);
            CP_COMMIT();
            CP_WAIT1();
        } else {
            CP_WAIT0();
        }
        __syncthreads();

        uint32_t stg = sb + (kt & 1) * STG;
        #pragma unroll
        for (int ksub = 0; ksub < 2; ksub++) {
            uint32_t koff = ksub * 32;
            uint32_t aH[2][4], aLr[2][4];
            #pragma unroll
            for (int mt = 0; mt < 2; mt++) {
                ldmx4(aH[mt],  stg + aRel[mt] + koff);
                ldmx4(aLr[mt], stg + aRel[mt] + koff + dL);
            }
            uint32_t bH[8][2], bL[8][2];
            #pragma unroll
            for (int ntp = 0; ntp < 4; ntp++) {
                uint32_t t[4];
                ldmx4(t, stg + bRel[ntp] + koff);
                bH[2*ntp][0] = t[0]; bH[2*ntp][1] = t[1];
                bH[2*ntp+1][0] = t[2]; bH[2*ntp+1][1] = t[3];
                ldmx4(t, stg + bRel[ntp] + koff + dL);
                bL[2*ntp][0] = t[0]; bL[2*ntp][1] = t[1];
                bL[2*ntp+1][0] = t[2]; bL[2*ntp+1][1] = t[3];
            }
            #pragma unroll
            for (int mt = 0; mt < 2; mt++)
                #pragma unroll
                for (int nt = 0; nt < 8; nt++)
                    mma_bf16(acc[mt][nt], aH[mt], bH[nt]);
            #pragma unroll
            for (int mt = 0; mt < 2; mt++)
                #pragma unroll
                for (int nt = 0; nt < 8; nt++)
                    mma_bf16(acc[mt][nt], aH[mt], bL[nt]);
            #pragma unroll
            for (int mt = 0; mt < 2; mt++)
                #pragma unroll
                for (int nt = 0; nt < 8; nt++)
                    mma_bf16(acc[mt][nt], aLr[mt], bH[nt]);
        }
        __syncthreads();
    }
#undef ISSUE_FILL

    // ---- epilogue ----
    const float bnmul = rsqrtf(1.0f + 1e-5f);
    #pragma unroll
    for (int nt = 0; nt < 8; nt++) {
        int col0 = colBase + warp_n * 64 + nt * 8 + 2 * tg;
        float b0 = __ldg(&bias[col0]);
        float b1 = __ldg(&bias[col0 + 1]);
        float g0 = 0.f, g1 = 0.f, be0 = 0.f, be1 = 0.f;
        if (BN_OUT) {
            g0 = __ldg(&gamma[col0]) * bnmul;     be0 = __ldg(&beta[col0]);
            g1 = __ldg(&gamma[col0 + 1]) * bnmul; be1 = __ldg(&beta[col0 + 1]);
        }
        #pragma unroll
        for (int mt = 0; mt < 2; mt++) {
            int r0 = rowBase + warp_m * 32 + mt * 16 + g;
            #pragma unroll
            for (int half = 0; half < 2; half++) {
                int row = r0 + half * 8;
                if (row < N) {
                    float v0 = fmaxf(acc[mt][nt][2 * half + 0] + b0, 0.f);
                    float v1 = fmaxf(acc[mt][nt][2 * half + 1] + b1, 0.f);
                    if (BN_OUT) { v0 = v0 * g0 + be0; v1 = v1 * g1 + be1; }
                    if (EPI_LIMB) {
                        float h0,l0,h1,l1;
                        split2(v0, h0, l0); split2(v1, h1, l1);
                        *(uint32_t*)&CH[(size_t)row * M + col0] = pkbf(h0, h1);
                        *(uint32_t*)&CL[(size_t)row * M + col0] = pkbf(l0, l1);
                    } else {
                        *(float2*)(Cf + (size_t)row * M + col0) = make_float2(v0, v1);
                    }
                }
            }
        }
    }
}

// ---------------- pooling (batch is sorted -> binary search ranges) ----------------
__device__ __forceinline__ int lbound(const int* a, int n, int v) {
    int lo = 0, hi = n;
    while (lo < hi) { int m = (lo + hi) >> 1; if (a[m] < v) lo = m + 1; else hi = m; }
    return lo;
}

__global__ void pool_k(const float* __restrict__ H, const int* __restrict__ batch) {
    int g = blockIdx.x;
    int t = threadIdx.x;
    __shared__ int ss, se;
    if (t == 0)  ss = lbound(batch, N_NODES, g);
    if (t == 32) se = lbound(batch, N_NODES, g + 1);
    __syncthreads();
    int start = ss, end = se;
    int c = t & 63, sub = t >> 6;
    const float4* h4 = (const float4*)H;
    float4 acc = make_float4(0.f, 0.f, 0.f, 0.f);
    for (int i = start + sub; i < end; i += 4) {
        float4 v = h4[(size_t)i * 64 + c];
        acc.x += v.x; acc.y += v.y; acc.z += v.z; acc.w += v.w;
    }
    __shared__ float4 red[256];
    red[t] = acc;
    __syncthreads();
    if (sub == 0) {
        float4 a = red[c], b = red[c + 64], c2 = red[c + 128], d = red[c + 192];
        int cnt = end - start;
        float inv = 1.0f / (float)(cnt > 1 ? cnt : 1);
        float4 o;
        o.x = (a.x + b.x + c2.x + d.x) * inv;
        o.y = (a.y + b.y + c2.y + d.y) * inv;
        o.z = (a.z + b.z + c2.z + d.z) * inv;
        o.w = (a.w + b.w + c2.w + d.w) * inv;
        ((float4*)g_pool)[g * 64 + c] = o;
    }
}

// ---------------- final MLP + log_softmax (one block per graph) ----------------
__global__ void final_k(const float* __restrict__ lw1, const float* __restrict__ lb1,
                        const float* __restrict__ lw2, const float* __restrict__ lb2,
                        float* __restrict__ out)
{
    int g = blockIdx.x, t = threadIdx.x;
    __shared__ float p[HID], o1[HID], o2[OUT_DIM];
    __shared__ float s_m, s_l;
    p[t] = g_pool[g * HID + t];
    __syncthreads();
    float acc = __ldg(&lb1[t]);
    for (int k = 0; k < HID; k++) acc = fmaf(p[k], __ldg(&lw1[k * HID + t]), acc);
    o1[t] = fmaxf(acc, 0.f);
    __syncthreads();
    if (t < OUT_DIM) {
        float a = __ldg(&lb2[t]);
        for (int k = 0; k < HID; k++) a = fmaf(o1[k], __ldg(&lw2[k * OUT_DIM + t]), a);
        o2[t] = a;
    }
    __syncthreads();
    if (t == 0) {
        float m = -1e30f;
        for (int j = 0; j < OUT_DIM; j++) m = fmaxf(m, o2[j]);
        float s = 0.f;
        for (int j = 0; j < OUT_DIM; j++) s += expf(o2[j] - m);
        s_m = m; s_l = logf(s);
    }
    __syncthreads();
    if (t < OUT_DIM) out[g * OUT_DIM + t] = o2[t] - s_m - s_l;
}

// ---------------- launcher ----------------
extern "C" void kernel_launch(void* const* d_in, const int* in_sizes, int n_in,
                              void* d_out, int out_size)
{
    const float* x    = (const float*)d_in[0];
    const int*   ei   = (const int*)  d_in[1];
    const int*   batch= (const int*)  d_in[2];
    const float* w1a  = (const float*)d_in[3];
    const float* b1a  = (const float*)d_in[4];
    const float* w2a  = (const float*)d_in[5];
    const float* b2a  = (const float*)d_in[6];
    const float* ga   = (const float*)d_in[7];
    const float* bba  = (const float*)d_in[8];
    const float* eps0 = (const float*)d_in[9];
    const float* w1r  = (const float*)d_in[10];
    const float* b1r  = (const float*)d_in[11];
    const float* w2r  = (const float*)d_in[12];
    const float* b2r  = (const float*)d_in[13];
    const float* gr   = (const float*)d_in[14];
    const float* br   = (const float*)d_in[15];
    const float* epsr = (const float*)d_in[16];
    const float* lw1  = (const float*)d_in[17];
    const float* lb1  = (const float*)d_in[18];
    const float* lw2  = (const float*)d_in[19];
    const float* lb2  = (const float*)d_in[20];
    float* out = (float*)d_out;

    const int* src = ei;
    const int* dst = ei + N_EDGES;

    void *hA_p, *hB_p, *AH_p, *AL_p, *TH_p, *TL_p, *WH_p, *WL_p;
    void *deg_p, *rp_p, *cur_p;
    cudaGetSymbolAddress(&hA_p, g_hA);
    cudaGetSymbolAddress(&hB_p, g_hB);
    cudaGetSymbolAddress(&AH_p, g_AH);
    cudaGetSymbolAddress(&AL_p, g_AL);
    cudaGetSymbolAddress(&TH_p, g_TH);
    cudaGetSymbolAddress(&TL_p, g_TL);
    cudaGetSymbolAddress(&WH_p, g_WH);
    cudaGetSymbolAddress(&WL_p, g_WL);
    cudaGetSymbolAddress(&deg_p, g_deg);
    cudaGetSymbolAddress(&rp_p,  g_rowptr);
    cudaGetSymbolAddress(&cur_p, g_cursor);

    float* hA = (float*)hA_p;
    float* hB = (float*)hB_p;
    __nv_bfloat16* AH = (__nv_bfloat16*)AH_p;
    __nv_bfloat16* AL = (__nv_bfloat16*)AL_p;
    __nv_bfloat16* TH = (__nv_bfloat16*)TH_p;
    __nv_bfloat16* TL = (__nv_bfloat16*)TL_p;
    __nv_bfloat16* WH = (__nv_bfloat16*)WH_p;
    __nv_bfloat16* WL = (__nv_bfloat16*)WL_p;

    static bool attr_done = false;
    if (!attr_done) {
        cudaFuncSetAttribute(gemm_p<true,  false>,
                             cudaFuncAttributeMaxDynamicSharedMemorySize, GSMEM);
        cudaFuncSetAttribute(gemm_p<false, true>,
                             cudaFuncAttributeMaxDynamicSharedMemorySize, GSMEM);
        attr_done = true;
    }

    // --- weight pre-split/transpose (once per call) ---
    const int OW1A = 0;                 // 256 x 128
    const int OW2A = 32768;             // 256 x 256
    const int OW1R = 98304;             // 3 x 256 x 256
    const int OW2R = 294912;            // 3 x 256 x 256
    wt_k<<<(32768 + 255) / 256, 256>>>(w1a, WH + OW1A, WL + OW1A, IN_DIM, HID);
    wt_k<<<(65536 + 255) / 256, 256>>>(w2a, WH + OW2A, WL + OW2A, HID, HID);
    for (int i = 0; i < 3; i++) {
        wt_k<<<(65536 + 255) / 256, 256>>>(w1r + (size_t)i * HID * HID,
                                           WH + OW1R + i * 65536, WL + OW1R + i * 65536,
                                           HID, HID);
        wt_k<<<(65536 + 255) / 256, 256>>>(w2r + (size_t)i * HID * HID,
                                           WH + OW2R + i * 65536, WL + OW2R + i * 65536,
                                           HID, HID);
    }

    // --- CSR build ---
    cudaMemsetAsync(deg_p, 0, N_NODES * sizeof(int));
    hist_k<<<(N_EDGES + 255) / 256, 256>>>(dst);
    scan_k<<<1, 1024>>>();
    cudaMemcpyAsync(cur_p, rp_p, N_NODES * sizeof(int), cudaMemcpyDeviceToDevice);
    fill_k<<<(N_EDGES + 255) / 256, 256>>>(src, dst);

    dim3 grid(HID / 128, (N_NODES + 127) / 128);   // (2, 391)

    // --- layer 1 ---
    aggf_k<<<(N_NODES * 32) / 256, 256>>>(x, eps0, IN_DIM / 4, AH, AL);
    gemm_p<true,  false><<<grid, 256, GSMEM>>>(AH, AL, WH + OW1A, WL + OW1A,
                                               b1a, nullptr, nullptr,
                                               nullptr, TH, TL, N_NODES, IN_DIM, HID);
    gemm_p<false, true ><<<grid, 256, GSMEM>>>(TH, TL, WH + OW2A, WL + OW2A,
                                               b2a, ga, bba,
                                               hA, nullptr, nullptr, N_NODES, HID, HID);

    // --- layers 2..4 ---
    const float* hin = hA;
    float* hout = hB;
    for (int i = 0; i < 3; i++) {
        aggf_k<<<(N_NODES * 64) / 256, 256>>>(hin, epsr + i, HID / 4, AH, AL);
        gemm_p<true,  false><<<grid, 256, GSMEM>>>(AH, AL,
                                                   WH + OW1R + i * 65536,
                                                   WL + OW1R + i * 65536,
                                                   b1r + i * HID, nullptr, nullptr,
                                                   nullptr, TH, TL, N_NODES, HID, HID);
        gemm_p<false, true ><<<grid, 256, GSMEM>>>(TH, TL,
                                                   WH + OW2R + i * 65536,
                                                   WL + OW2R + i * 65536,
                                                   b2r + i * HID,
                                                   gr + i * HID, br + i * HID,
                                                   hout, nullptr, nullptr,
                                                   N_NODES, HID, HID);
        const float* t2 = hin; hin = hout; hout = (float*)t2;
    }

    // --- pooling + head ---
    pool_k<<<N_GRAPHS, 256>>>(hin, batch);
    final_k<<<N_GRAPHS, 256>>>(lw1, lb1, lw2, lb2, out);
}

// round 10
// speedup vs baseline: 2.0709x; 1.1261x over previous
#include <cuda_runtime.h>
#include <cuda_bf16.h>
#include <math.h>
#include <stdint.h>

#define N_NODES  50000
#define N_EDGES  800000
#define N_GRAPHS 512
#define IN_DIM   128
#define HID      256
#define OUT_DIM  40

// ---------------- scratch (device globals; no allocation allowed) ----------------
__device__ float g_hA [(size_t)N_NODES * HID];
__device__ float g_hB [(size_t)N_NODES * HID];
__device__ __nv_bfloat16 g_AH[(size_t)N_NODES * HID];
__device__ __nv_bfloat16 g_AL[(size_t)N_NODES * HID];
__device__ __nv_bfloat16 g_TH[(size_t)N_NODES * HID];
__device__ __nv_bfloat16 g_TL[(size_t)N_NODES * HID];
#define W_TOTAL 491520   // 256x128 + 7x 256x256, transposed K-major
__device__ __nv_bfloat16 g_WH[W_TOTAL];
__device__ __nv_bfloat16 g_WL[W_TOTAL];
__device__ int   g_deg[N_NODES];
__device__ int   g_rowptr[N_NODES + 1];
__device__ int   g_cursor[N_NODES];
__device__ int   g_eidx[N_EDGES];
__device__ float g_pool[N_GRAPHS * HID];

// ---------------- helpers ----------------
__device__ __forceinline__ uint32_t pkbf(float a, float b) {
    __nv_bfloat162 t = __floats2bfloat162_rn(a, b);
    uint32_t u; memcpy(&u, &t, 4); return u;
}
__device__ __forceinline__ void split2(float v, float& h, float& l) {
    h = __bfloat162float(__float2bfloat16(v));
    l = v - h;
}
__device__ __forceinline__ uint32_t s2u(const void* p) {
    uint32_t a;
    asm("{ .reg .u64 t; cvta.to.shared.u64 t, %1; cvt.u32.u64 %0, t; }"
        : "=r"(a) : "l"(p));
    return a;
}
__device__ __forceinline__ void ldmx4(uint32_t* r, uint32_t addr) {
    asm volatile("ldmatrix.sync.aligned.m8n8.x4.shared.b16 {%0,%1,%2,%3}, [%4];"
                 : "=r"(r[0]), "=r"(r[1]), "=r"(r[2]), "=r"(r[3]) : "r"(addr));
}
__device__ __forceinline__ void mma_bf16(float* c, const uint32_t* a, const uint32_t* b) {
    asm volatile(
        "mma.sync.aligned.m16n8k16.row.col.f32.bf16.bf16.f32 "
        "{%0,%1,%2,%3}, {%4,%5,%6,%7}, {%8,%9}, {%0,%1,%2,%3};"
        : "+f"(c[0]), "+f"(c[1]), "+f"(c[2]), "+f"(c[3])
        : "r"(a[0]), "r"(a[1]), "r"(a[2]), "r"(a[3]), "r"(b[0]), "r"(b[1]));
}
__device__ __forceinline__ void cpa16(uint32_t dst, const void* src, uint32_t vsz) {
    asm volatile("cp.async.cg.shared.global [%0], [%1], 16, %2;"
                 :: "r"(dst), "l"(src), "r"(vsz));
}
#define CP_COMMIT() asm volatile("cp.async.commit_group;" ::: "memory")
#define CP_WAIT1()  asm volatile("cp.async.wait_group 1;" ::: "memory")
#define CP_WAIT0()  asm volatile("cp.async.wait_group 0;" ::: "memory")

// ---------------- CSR build ----------------
__global__ void hist_k(const int* __restrict__ dst) {
    int e = blockIdx.x * blockDim.x + threadIdx.x;
    if (e < N_EDGES) atomicAdd(&g_deg[dst[e]], 1);
}

__global__ void scan_k() {
    __shared__ int buf[1024];
    __shared__ int carry;
    int tid = threadIdx.x;
    if (tid == 0) carry = 0;
    __syncthreads();
    for (int base = 0; base < N_NODES; base += 1024) {
        int v = (base + tid < N_NODES) ? g_deg[base + tid] : 0;
        buf[tid] = v;
        __syncthreads();
        for (int off = 1; off < 1024; off <<= 1) {
            int t = (tid >= off) ? buf[tid - off] : 0;
            __syncthreads();
            buf[tid] += t;
            __syncthreads();
        }
        int c0 = carry;
        if (base + tid < N_NODES) g_rowptr[base + tid] = buf[tid] - v + c0;
        __syncthreads();
        if (tid == 0) carry += buf[1023];
        __syncthreads();
    }
    if (tid == 0) g_rowptr[N_NODES] = carry;
}

__global__ void fill_k(const int* __restrict__ src, const int* __restrict__ dst) {
    int e = blockIdx.x * blockDim.x + threadIdx.x;
    if (e < N_EDGES) {
        int d = dst[e];
        int p = atomicAdd(&g_cursor[d], 1);
        g_eidx[p] = src[e];
    }
}

// ---------------- fused weight pre-split + transpose (all 8 matrices) ----------------
// layout in g_WH/g_WL: [w1a 256x128][w2a 256x256][w1r x3][w2r x3], dst[n][k]=W[k][n]
__global__ void wt_all(const float* __restrict__ w1a, const float* __restrict__ w2a,
                       const float* __restrict__ w1r, const float* __restrict__ w2r,
                       __nv_bfloat16* __restrict__ dH, __nv_bfloat16* __restrict__ dL) {
    int idx = blockIdx.x * blockDim.x + threadIdx.x;
    if (idx >= W_TOTAL) return;
    const float* W; int K, loc;
    if (idx < 32768)       { W = w1a; K = 128; loc = idx; }
    else if (idx < 98304)  { W = w2a; K = 256; loc = idx - 32768; }
    else if (idx < 294912) { int r = idx - 98304;  W = w1r + (r >> 16) * 65536; K = 256; loc = r & 65535; }
    else                   { int r = idx - 294912; W = w2r + (r >> 16) * 65536; K = 256; loc = r & 65535; }
    int n = loc / K, k = loc - n * K;
    float v = __ldg(&W[(size_t)k * HID + n]);
    float h, l; split2(v, h, l);
    dH[idx] = __float2bfloat16(h);
    dL[idx] = __float2bfloat16(l);
}

// ---------------- fused aggregation + GIN add + limb split ----------------
__global__ void aggf_k(const float* __restrict__ X, const float* __restrict__ epsp,
                       int D4, __nv_bfloat16* __restrict__ AH,
                       __nv_bfloat16* __restrict__ AL) {
    int gid  = blockIdx.x * blockDim.x + threadIdx.x;
    int node = gid / D4;
    int c    = gid - node * D4;
    int s = g_rowptr[node];
    int e = g_rowptr[node + 1];
    const float4* x4 = (const float4*)X;
    float4 acc0 = make_float4(0.f, 0.f, 0.f, 0.f);
    float4 acc1 = make_float4(0.f, 0.f, 0.f, 0.f);
    int j = s;
    for (; j + 1 < e; j += 2) {
        int s0 = g_eidx[j];
        int s1 = g_eidx[j + 1];
        float4 v0 = __ldg(&x4[(size_t)s0 * D4 + c]);
        float4 v1 = __ldg(&x4[(size_t)s1 * D4 + c]);
        acc0.x += v0.x; acc0.y += v0.y; acc0.z += v0.z; acc0.w += v0.w;
        acc1.x += v1.x; acc1.y += v1.y; acc1.z += v1.z; acc1.w += v1.w;
    }
    if (j < e) {
        int s0 = g_eidx[j];
        float4 v0 = __ldg(&x4[(size_t)s0 * D4 + c]);
        acc0.x += v0.x; acc0.y += v0.y; acc0.z += v0.z; acc0.w += v0.w;
    }
    float alpha = 1.0f + __ldg(epsp);
    float4 xs = __ldg(&x4[(size_t)node * D4 + c]);
    float4 v;
    v.x = alpha * xs.x + acc0.x + acc1.x;
    v.y = alpha * xs.y + acc0.y + acc1.y;
    v.z = alpha * xs.z + acc0.z + acc1.z;
    v.w = alpha * xs.w + acc0.w + acc1.w;
    float h0,l0,h1,l1,h2,l2,h3,l3;
    split2(v.x,h0,l0); split2(v.y,h1,l1); split2(v.z,h2,l2); split2(v.w,h3,l3);
    size_t base = (size_t)node * (D4 * 4) + c * 4;
    *(uint2*)&AH[base] = make_uint2(pkbf(h0, h1), pkbf(h2, h3));
    *(uint2*)&AL[base] = make_uint2(pkbf(l0, l1), pkbf(l2, l3));
}

// ---------------- pipelined bf16 2-limb tensor GEMM (occupancy 2) ----------------
#define KT 32
#define OAH 0u
#define OAL 10240u
#define OBH 20480u
#define OBL 30720u
#define STG 40960u
#define GSMEM (2 * STG)

template<bool EPI_LIMB, bool BN_OUT>
__global__ void __launch_bounds__(256, 2) gemm_p(
    const __nv_bfloat16* __restrict__ AH, const __nv_bfloat16* __restrict__ AL,
    const __nv_bfloat16* __restrict__ WH, const __nv_bfloat16* __restrict__ WL,
    const float* __restrict__ bias,
    const float* __restrict__ gamma, const float* __restrict__ beta,
    float* __restrict__ Cf, __nv_bfloat16* __restrict__ CH,
    __nv_bfloat16* __restrict__ CL,
    int N, int K, int M)
{
    extern __shared__ char smem[];
    uint32_t sb = s2u(smem);
    int tid = threadIdx.x;
    int lane = tid & 31;
    int wid  = tid >> 5;
    int warp_m = wid & 3;
    int warp_n = wid >> 2;
    int g  = lane >> 2;
    int tg = lane & 3;

    int rowBase = blockIdx.y * 128;
    int colBase = blockIdx.x * 128;

    int fr = tid >> 1;
    int fk = (tid & 1) * 16;
    bool avalid = (rowBase + fr) < N;
    size_t aBase = (size_t)(avalid ? (rowBase + fr) : 0) * K + fk;
    size_t bBase = (size_t)(colBase + fr) * K + fk;
    uint32_t avsz = avalid ? 16u : 0u;
    uint32_t aDst = fr * 80 + fk * 2;

#define ISSUE_FILL(stage, k0) do {                                      \
    uint32_t s_ = sb + (stage) * STG;                                   \
    const char* pAH = (const char*)(AH + aBase + (k0));                 \
    const char* pAL = (const char*)(AL + aBase + (k0));                 \
    cpa16(s_ + OAH + aDst,      pAH,      avsz);                        \
    cpa16(s_ + OAH + aDst + 16, pAH + 16, avsz);                        \
    cpa16(s_ + OAL + aDst,      pAL,      avsz);                        \
    cpa16(s_ + OAL + aDst + 16, pAL + 16, avsz);                        \
    const char* pBH = (const char*)(WH + bBase + (k0));                 \
    const char* pBL = (const char*)(WL + bBase + (k0));                 \
    cpa16(s_ + OBH + aDst,      pBH,      16u);                         \
    cpa16(s_ + OBH + aDst + 16, pBH + 16, 16u);                         \
    cpa16(s_ + OBL + aDst,      pBL,      16u);                         \
    cpa16(s_ + OBL + aDst + 16, pBL + 16, 16u);                         \
} while (0)

    float acc[2][8][4];
    #pragma unroll
    for (int mt = 0; mt < 2; mt++)
        #pragma unroll
        for (int nt = 0; nt < 8; nt++)
            #pragma unroll
            for (int q = 0; q < 4; q++) acc[mt][nt][q] = 0.f;

    uint32_t aRel[2];
    #pragma unroll
    for (int mt = 0; mt < 2; mt++) {
        int r = warp_m * 32 + mt * 16 + (lane & 15);
        int c = (lane >> 4) * 8;
        aRel[mt] = OAH + r * 80 + c * 2;
    }
    uint32_t bRel[4];
    #pragma unroll
    for (int ntp = 0; ntp < 4; ntp++) {
        int n = warp_n * 64 + ntp * 16 + (lane >> 4) * 8 + (lane & 7);
        int c = ((lane >> 3) & 1) * 8;
        bRel[ntp] = OBH + n * 80 + c * 2;
    }
    const uint32_t dL = OAL - OAH;

    ISSUE_FILL(0, 0);
    CP_COMMIT();

    const int nkt = K / KT;
    for (int kt = 0; kt < nkt; kt++) {
        if (kt + 1 < nkt) {
            ISSUE_FILL((kt + 1) & 1, (kt + 1) * KT);
            CP_COMMIT();
            CP_WAIT1();
        } else {
            CP_WAIT0();
        }
        __syncthreads();

        uint32_t stg = sb + (kt & 1) * STG;
        #pragma unroll
        for (int ksub = 0; ksub < 2; ksub++) {
            uint32_t koff = ksub * 32;
            uint32_t aH[2][4], aLr[2][4];
            #pragma unroll
            for (int mt = 0; mt < 2; mt++) {
                ldmx4(aH[mt],  stg + aRel[mt] + koff);
                ldmx4(aLr[mt], stg + aRel[mt] + koff + dL);
            }
            // ---- bH passes first (hh, lh), so bH dies before bL loads ----
            {
                uint32_t bH[8][2];
                #pragma unroll
                for (int ntp = 0; ntp < 4; ntp++) {
                    uint32_t t[4];
                    ldmx4(t, stg + bRel[ntp] + koff);
                    bH[2*ntp][0] = t[0]; bH[2*ntp][1] = t[1];
                    bH[2*ntp+1][0] = t[2]; bH[2*ntp+1][1] = t[3];
                }
                #pragma unroll
                for (int mt = 0; mt < 2; mt++)
                    #pragma unroll
                    for (int nt = 0; nt < 8; nt++)
                        mma_bf16(acc[mt][nt], aH[mt], bH[nt]);
                #pragma unroll
                for (int mt = 0; mt < 2; mt++)
                    #pragma unroll
                    for (int nt = 0; nt < 8; nt++)
                        mma_bf16(acc[mt][nt], aLr[mt], bH[nt]);
            }
            // ---- hl pass ----
            {
                uint32_t bL[8][2];
                #pragma unroll
                for (int ntp = 0; ntp < 4; ntp++) {
                    uint32_t t[4];
                    ldmx4(t, stg + bRel[ntp] + koff + dL);
                    bL[2*ntp][0] = t[0]; bL[2*ntp][1] = t[1];
                    bL[2*ntp+1][0] = t[2]; bL[2*ntp+1][1] = t[3];
                }
                #pragma unroll
                for (int mt = 0; mt < 2; mt++)
                    #pragma unroll
                    for (int nt = 0; nt < 8; nt++)
                        mma_bf16(acc[mt][nt], aH[mt], bL[nt]);
            }
        }
        __syncthreads();
    }
#undef ISSUE_FILL

    // ---- epilogue ----
    const float bnmul = rsqrtf(1.0f + 1e-5f);
    #pragma unroll
    for (int nt = 0; nt < 8; nt++) {
        int col0 = colBase + warp_n * 64 + nt * 8 + 2 * tg;
        float b0 = __ldg(&bias[col0]);
        float b1 = __ldg(&bias[col0 + 1]);
        float g0 = 0.f, g1 = 0.f, be0 = 0.f, be1 = 0.f;
        if (BN_OUT) {
            g0 = __ldg(&gamma[col0]) * bnmul;     be0 = __ldg(&beta[col0]);
            g1 = __ldg(&gamma[col0 + 1]) * bnmul; be1 = __ldg(&beta[col0 + 1]);
        }
        #pragma unroll
        for (int mt = 0; mt < 2; mt++) {
            int r0 = rowBase + warp_m * 32 + mt * 16 + g;
            #pragma unroll
            for (int half = 0; half < 2; half++) {
                int row = r0 + half * 8;
                if (row < N) {
                    float v0 = fmaxf(acc[mt][nt][2 * half + 0] + b0, 0.f);
                    float v1 = fmaxf(acc[mt][nt][2 * half + 1] + b1, 0.f);
                    if (BN_OUT) { v0 = v0 * g0 + be0; v1 = v1 * g1 + be1; }
                    if (EPI_LIMB) {
                        float h0,l0,h1,l1;
                        split2(v0, h0, l0); split2(v1, h1, l1);
                        *(uint32_t*)&CH[(size_t)row * M + col0] = pkbf(h0, h1);
                        *(uint32_t*)&CL[(size_t)row * M + col0] = pkbf(l0, l1);
                    } else {
                        *(float2*)(Cf + (size_t)row * M + col0) = make_float2(v0, v1);
                    }
                }
            }
        }
    }
}

// ---------------- pooling ----------------
__device__ __forceinline__ int lbound(const int* a, int n, int v) {
    int lo = 0, hi = n;
    while (lo < hi) { int m = (lo + hi) >> 1; if (a[m] < v) lo = m + 1; else hi = m; }
    return lo;
}

__global__ void pool_k(const float* __restrict__ H, const int* __restrict__ batch) {
    int g = blockIdx.x;
    int t = threadIdx.x;
    __shared__ int ss, se;
    if (t == 0)  ss = lbound(batch, N_NODES, g);
    if (t == 32) se = lbound(batch, N_NODES, g + 1);
    __syncthreads();
    int start = ss, end = se;
    int c = t & 63, sub = t >> 6;
    const float4* h4 = (const float4*)H;
    float4 acc = make_float4(0.f, 0.f, 0.f, 0.f);
    for (int i = start + sub; i < end; i += 4) {
        float4 v = h4[(size_t)i * 64 + c];
        acc.x += v.x; acc.y += v.y; acc.z += v.z; acc.w += v.w;
    }
    __shared__ float4 red[256];
    red[t] = acc;
    __syncthreads();
    if (sub == 0) {
        float4 a = red[c], b = red[c + 64], c2 = red[c + 128], d = red[c + 192];
        int cnt = end - start;
        float inv = 1.0f / (float)(cnt > 1 ? cnt : 1);
        float4 o;
        o.x = (a.x + b.x + c2.x + d.x) * inv;
        o.y = (a.y + b.y + c2.y + d.y) * inv;
        o.z = (a.z + b.z + c2.z + d.z) * inv;
        o.w = (a.w + b.w + c2.w + d.w) * inv;
        ((float4*)g_pool)[g * 64 + c] = o;
    }
}

// ---------------- final MLP + log_softmax ----------------
__global__ void final_k(const float* __restrict__ lw1, const float* __restrict__ lb1,
                        const float* __restrict__ lw2, const float* __restrict__ lb2,
                        float* __restrict__ out)
{
    int g = blockIdx.x, t = threadIdx.x;
    __shared__ float p[HID], o1[HID], o2[OUT_DIM];
    __shared__ float s_m, s_l;
    p[t] = g_pool[g * HID + t];
    __syncthreads();
    float acc = __ldg(&lb1[t]);
    for (int k = 0; k < HID; k++) acc = fmaf(p[k], __ldg(&lw1[k * HID + t]), acc);
    o1[t] = fmaxf(acc, 0.f);
    __syncthreads();
    if (t < OUT_DIM) {
        float a = __ldg(&lb2[t]);
        for (int k = 0; k < HID; k++) a = fmaf(o1[k], __ldg(&lw2[k * OUT_DIM + t]), a);
        o2[t] = a;
    }
    __syncthreads();
    if (t == 0) {
        float m = -1e30f;
        for (int j = 0; j < OUT_DIM; j++) m = fmaxf(m, o2[j]);
        float s = 0.f;
        for (int j = 0; j < OUT_DIM; j++) s += expf(o2[j] - m);
        s_m = m; s_l = logf(s);
    }
    __syncthreads();
    if (t < OUT_DIM) out[g * OUT_DIM + t] = o2[t] - s_m - s_l;
}

// ---------------- launcher ----------------
extern "C" void kernel_launch(void* const* d_in, const int* in_sizes, int n_in,
                              void* d_out, int out_size)
{
    const float* x    = (const float*)d_in[0];
    const int*   ei   = (const int*)  d_in[1];
    const int*   batch= (const int*)  d_in[2];
    const float* w1a  = (const float*)d_in[3];
    const float* b1a  = (const float*)d_in[4];
    const float* w2a  = (const float*)d_in[5];
    const float* b2a  = (const float*)d_in[6];
    const float* ga   = (const float*)d_in[7];
    const float* bba  = (const float*)d_in[8];
    const float* eps0 = (const float*)d_in[9];
    const float* w1r  = (const float*)d_in[10];
    const float* b1r  = (const float*)d_in[11];
    const float* w2r  = (const float*)d_in[12];
    const float* b2r  = (const float*)d_in[13];
    const float* gr   = (const float*)d_in[14];
    const float* br   = (const float*)d_in[15];
    const float* epsr = (const float*)d_in[16];
    const float* lw1  = (const float*)d_in[17];
    const float* lb1  = (const float*)d_in[18];
    const float* lw2  = (const float*)d_in[19];
    const float* lb2  = (const float*)d_in[20];
    float* out = (float*)d_out;

    const int* src = ei;
    const int* dst = ei + N_EDGES;

    void *hA_p, *hB_p, *AH_p, *AL_p, *TH_p, *TL_p, *WH_p, *WL_p;
    void *deg_p, *rp_p, *cur_p;
    cudaGetSymbolAddress(&hA_p, g_hA);
    cudaGetSymbolAddress(&hB_p, g_hB);
    cudaGetSymbolAddress(&AH_p, g_AH);
    cudaGetSymbolAddress(&AL_p, g_AL);
    cudaGetSymbolAddress(&TH_p, g_TH);
    cudaGetSymbolAddress(&TL_p, g_TL);
    cudaGetSymbolAddress(&WH_p, g_WH);
    cudaGetSymbolAddress(&WL_p, g_WL);
    cudaGetSymbolAddress(&deg_p, g_deg);
    cudaGetSymbolAddress(&rp_p,  g_rowptr);
    cudaGetSymbolAddress(&cur_p, g_cursor);

    float* hA = (float*)hA_p;
    float* hB = (float*)hB_p;
    __nv_bfloat16* AH = (__nv_bfloat16*)AH_p;
    __nv_bfloat16* AL = (__nv_bfloat16*)AL_p;
    __nv_bfloat16* TH = (__nv_bfloat16*)TH_p;
    __nv_bfloat16* TL = (__nv_bfloat16*)TL_p;
    __nv_bfloat16* WH = (__nv_bfloat16*)WH_p;
    __nv_bfloat16* WL = (__nv_bfloat16*)WL_p;

    static bool attr_done = false;
    if (!attr_done) {
        cudaFuncSetAttribute(gemm_p<true,  false>,
                             cudaFuncAttributeMaxDynamicSharedMemorySize, GSMEM);
        cudaFuncSetAttribute(gemm_p<false, true>,
                             cudaFuncAttributeMaxDynamicSharedMemorySize, GSMEM);
        attr_done = true;
    }

    // --- weight pre-split/transpose (single fused launch) ---
    wt_all<<<(W_TOTAL + 255) / 256, 256>>>(w1a, w2a, w1r, w2r, WH, WL);

    // --- CSR build ---
    cudaMemsetAsync(deg_p, 0, N_NODES * sizeof(int));
    hist_k<<<(N_EDGES + 255) / 256, 256>>>(dst);
    scan_k<<<1, 1024>>>();
    cudaMemcpyAsync(cur_p, rp_p, N_NODES * sizeof(int), cudaMemcpyDeviceToDevice);
    fill_k<<<(N_EDGES + 255) / 256, 256>>>(src, dst);

    const int OW1A = 0;
    const int OW2A = 32768;
    const int OW1R = 98304;
    const int OW2R = 294912;

    dim3 grid(HID / 128, (N_NODES + 127) / 128);   // (2, 391)

    // --- layer 1 ---
    aggf_k<<<(N_NODES * 32) / 256, 256>>>(x, eps0, IN_DIM / 4, AH, AL);
    gemm_p<true,  false><<<grid, 256, GSMEM>>>(AH, AL, WH + OW1A, WL + OW1A,
                                               b1a, nullptr, nullptr,
                                               nullptr, TH, TL, N_NODES, IN_DIM, HID);
    gemm_p<false, true ><<<grid, 256, GSMEM>>>(TH, TL, WH + OW2A, WL + OW2A,
                                               b2a, ga, bba,
                                               hA, nullptr, nullptr, N_NODES, HID, HID);

    // --- layers 2..4 ---
    const float* hin = hA;
    float* hout = hB;
    for (int i = 0; i < 3; i++) {
        aggf_k<<<(N_NODES * 64) / 256, 256>>>(hin, epsr + i, HID / 4, AH, AL);
        gemm_p<true,  false><<<grid, 256, GSMEM>>>(AH, AL,
                                                   WH + OW1R + i * 65536,
                                                   WL + OW1R + i * 65536,
                                                   b1r + i * HID, nullptr, nullptr,
                                                   nullptr, TH, TL, N_NODES, HID, HID);
        gemm_p<false, true ><<<grid, 256, GSMEM>>>(TH, TL,
                                                   WH + OW2R + i * 65536,
                                                   WL + OW2R + i * 65536,
                                                   b2r + i * HID,
                                                   gr + i * HID, br + i * HID,
                                                   hout, nullptr, nullptr,
                                                   N_NODES, HID, HID);
        const float* t2 = hin; hin = hout; hout = (float*)t2;
    }

    // --- pooling + head ---
    pool_k<<<N_GRAPHS, 256>>>(hin, batch);
    final_k<<<N_GRAPHS, 256>>>(lw1, lb1, lw2, lb2, out);
}